// round 2
// baseline (speedup 1.0000x reference)
#include <cuda_runtime.h>
#include <cuda_bf16.h>
#include <cstdint>

// Problem constants
#define B_  128
#define T_  100
#define E_  128
#define F_  700
#define S_  400
#define V_  10000

// ---------------------------------------------------------------------------
// Scratch (static device globals; no runtime allocation)
// ---------------------------------------------------------------------------
__device__ float g_fh[B_ * F_];
__device__ float g_fc[B_ * F_];
__device__ float g_sh[B_ * S_];
__device__ float g_sc[B_ * S_];
__device__ float g_z [B_ * 4 * F_];   // gate pre-activations for fast cells
__device__ float g_zS[B_ * 4 * S_];   // gate pre-activations for slow cell
__device__ float g_hist[(size_t)B_ * T_ * F_]; // fh history, row = b*T + t

// ---------------------------------------------------------------------------
// Helpers
// ---------------------------------------------------------------------------
__device__ __forceinline__ float sigm(float x) { return 1.0f / (1.0f + __expf(-x)); }

__device__ __forceinline__ float blockReduceSum(float v, float* red) {
    int lane = threadIdx.x & 31;
    int w    = threadIdx.x >> 5;
    #pragma unroll
    for (int o = 16; o > 0; o >>= 1) v += __shfl_down_sync(0xffffffffu, v, o);
    if (lane == 0) red[w] = v;
    __syncthreads();
    float r = 0.0f;
    if (w == 0) {
        int nw = blockDim.x >> 5;
        r = (lane < nw) ? red[lane] : 0.0f;
        #pragma unroll
        for (int o = 16; o > 0; o >>= 1) r += __shfl_down_sync(0xffffffffu, r, o);
        if (lane == 0) red[0] = r;
    }
    __syncthreads();
    r = red[0];
    __syncthreads();
    return r;
}

// ---------------------------------------------------------------------------
// GEMM: C[M,N] = concat(A1[:,0:K1], A2[:,0:K2]) @ W[K,N] + bias[N]
// W row-major with leading dim N. Handles arbitrary bounds.
// ---------------------------------------------------------------------------
template <int BM, int BN, int BK, int TM, int TN>
__global__ void __launch_bounds__((BM / TM) * (BN / TN))
gemm_cat(const float* __restrict__ A1, int lda1, int K1,
         const float* __restrict__ A2, int lda2, int K2,
         const float* __restrict__ W,
         const float* __restrict__ bias,
         float* __restrict__ C, int M, int N, int ldc)
{
    constexpr int THREADS = (BM / TM) * (BN / TN);
    __shared__ float As[BK][BM + 4];
    __shared__ float Ws[BK][BN + 4];

    const int K  = K1 + K2;
    const int n0 = blockIdx.x * BN;
    const int m0 = blockIdx.y * BM;
    const int tid = threadIdx.x;
    const int tc  = tid % (BN / TN);
    const int tr  = tid / (BN / TN);

    float acc[TM][TN];
    #pragma unroll
    for (int i = 0; i < TM; i++)
        #pragma unroll
        for (int j = 0; j < TN; j++) acc[i][j] = 0.0f;

    for (int k0 = 0; k0 < K; k0 += BK) {
        // Load A tile (k fastest for coalescing)
        #pragma unroll
        for (int l = 0; l < (BM * BK) / THREADS; l++) {
            int i = tid + l * THREADS;
            int k = i % BK;
            int m = i / BK;
            int gm = m0 + m, gk = k0 + k;
            float v = 0.0f;
            if (gm < M && gk < K) {
                v = (gk < K1) ? A1[(size_t)gm * lda1 + gk]
                              : A2[(size_t)gm * lda2 + (gk - K1)];
            }
            As[k][m] = v;
        }
        // Load W tile (n fastest: coalesced)
        #pragma unroll
        for (int l = 0; l < (BK * BN) / THREADS; l++) {
            int i = tid + l * THREADS;
            int n = i % BN;
            int k = i / BN;
            int gk = k0 + k, gn = n0 + n;
            Ws[k][n] = (gk < K && gn < N) ? W[(size_t)gk * N + gn] : 0.0f;
        }
        __syncthreads();

        #pragma unroll
        for (int k = 0; k < BK; k++) {
            float a[TM], b[TN];
            #pragma unroll
            for (int i = 0; i < TM; i++) a[i] = As[k][tr * TM + i];
            #pragma unroll
            for (int j = 0; j < TN; j++) b[j] = Ws[k][tc * TN + j];
            #pragma unroll
            for (int i = 0; i < TM; i++)
                #pragma unroll
                for (int j = 0; j < TN; j++)
                    acc[i][j] = fmaf(a[i], b[j], acc[i][j]);
        }
        __syncthreads();
    }

    #pragma unroll
    for (int i = 0; i < TM; i++) {
        int gm = m0 + tr * TM + i;
        if (gm >= M) continue;
        #pragma unroll
        for (int j = 0; j < TN; j++) {
            int gn = n0 + tc * TN + j;
            if (gn < N) C[(size_t)gm * ldc + gn] = acc[i][j] + bias[gn];
        }
    }
}

// ---------------------------------------------------------------------------
// Fused LN-LSTM pointwise: per batch-row block.
//   z[B,4H] -> LN4 -> gates -> c update -> LN(c) -> h update -> zoneout
// ---------------------------------------------------------------------------
__global__ void __launch_bounds__(256)
lstm_pw(const float* __restrict__ z,
        float* __restrict__ h, float* __restrict__ c,
        const float* __restrict__ gg, const float* __restrict__ bg,
        const float* __restrict__ gc, const float* __restrict__ bc,
        int H,
        float* __restrict__ hist, int t, int T)
{
    const int b = blockIdx.x;
    const float* zb = z + (size_t)b * 4 * H;
    __shared__ float red[32];

    const float invH = 1.0f / (float)H;

    // per-chunk mean/var
    float s[4] = {0, 0, 0, 0}, q[4] = {0, 0, 0, 0};
    for (int u = threadIdx.x; u < H; u += blockDim.x) {
        #pragma unroll
        for (int ch = 0; ch < 4; ch++) {
            float v = zb[ch * H + u];
            s[ch] += v;
            q[ch] += v * v;
        }
    }
    float mu[4], rs[4];
    #pragma unroll
    for (int ch = 0; ch < 4; ch++) {
        float sm = blockReduceSum(s[ch], red);
        float sq = blockReduceSum(q[ch], red);
        mu[ch] = sm * invH;
        float var = sq * invH - mu[ch] * mu[ch];
        rs[ch] = rsqrtf(var + 1e-5f);
    }

    // gates + c update; keep new_c and sigmoid(o) in registers
    float nc_r[3], so_r[3];
    float sc_acc = 0.0f, qc_acc = 0.0f;
    #pragma unroll
    for (int it = 0; it < 3; it++) {
        int u = threadIdx.x + it * 256;
        if (u < H) {
            float iv = (zb[0 * H + u] - mu[0]) * rs[0] * gg[0 * H + u] + bg[0 * H + u];
            float jv = (zb[1 * H + u] - mu[1]) * rs[1] * gg[1 * H + u] + bg[1 * H + u];
            float fv = (zb[2 * H + u] - mu[2]) * rs[2] * gg[2 * H + u] + bg[2 * H + u];
            float ov = (zb[3 * H + u] - mu[3]) * rs[3] * gg[3 * H + u] + bg[3 * H + u];
            float cold = c[(size_t)b * H + u];
            float nc = cold * sigm(fv + 1.0f) + sigm(iv) * tanhf(jv);
            nc_r[it] = nc;
            so_r[it] = sigm(ov);
            sc_acc += nc;
            qc_acc += nc * nc;
        }
    }
    float smc = blockReduceSum(sc_acc, red);
    float sqc = blockReduceSum(qc_acc, red);
    float muc = smc * invH;
    float rsc = rsqrtf(sqc * invH - muc * muc + 1e-5f);

    #pragma unroll
    for (int it = 0; it < 3; it++) {
        int u = threadIdx.x + it * 256;
        if (u < H) {
            float nc = nc_r[it];
            float nh = tanhf((nc - muc) * rsc * gc[u] + bc[u]) * so_r[it];
            float hold = h[(size_t)b * H + u];
            float cold = c[(size_t)b * H + u];
            float hn = 0.9f * nh + 0.1f * hold;
            float cn = 0.5f * nc + 0.5f * cold;
            h[(size_t)b * H + u] = hn;
            c[(size_t)b * H + u] = cn;
            if (hist) hist[((size_t)b * T + t) * H + u] = hn;
        }
    }
}

// ---------------------------------------------------------------------------
// State init + tail copy
// ---------------------------------------------------------------------------
__global__ void init_states()
{
    int i = blockIdx.x * blockDim.x + threadIdx.x;
    int nF = B_ * F_, nS = B_ * S_;
    if (i < nF) { g_fh[i] = 0.0f; g_fc[i] = 0.0f; }
    if (i < nS) { g_sh[i] = 0.0f; g_sc[i] = 0.0f; }
}

__global__ void tail_copy(float* __restrict__ out, size_t out_total)
{
    int i = blockIdx.x * blockDim.x + threadIdx.x;
    const size_t base = (size_t)B_ * T_ * V_;
    const int nF = B_ * F_, nS = B_ * S_;
    const int total = 2 * nF + 2 * nS;
    if (i >= total) return;
    float v;
    size_t off = base + i;
    if (i < nF)                 v = g_fh[i];
    else if (i < 2 * nF)        v = g_fc[i - nF];
    else if (i < 2 * nF + nS)   v = g_sh[i - 2 * nF];
    else                        v = g_sc[i - 2 * nF - nS];
    if (off < out_total) out[off] = v;
}

// ---------------------------------------------------------------------------
// Launch
// ---------------------------------------------------------------------------
extern "C" void kernel_launch(void* const* d_in, const int* in_sizes, int n_in,
                              void* d_out, int out_size)
{
    const float* inputs = (const float*)d_in[0];
    const float* W0  = (const float*)d_in[1];
    const float* b0  = (const float*)d_in[2];
    const float* g0  = (const float*)d_in[3];
    const float* bg0 = (const float*)d_in[4];
    const float* gc0 = (const float*)d_in[5];
    const float* bc0 = (const float*)d_in[6];
    const float* W1  = (const float*)d_in[7];
    const float* b1  = (const float*)d_in[8];
    const float* g1  = (const float*)d_in[9];
    const float* bg1 = (const float*)d_in[10];
    const float* gc1 = (const float*)d_in[11];
    const float* bc1 = (const float*)d_in[12];
    const float* WS  = (const float*)d_in[13];
    const float* bS  = (const float*)d_in[14];
    const float* gS  = (const float*)d_in[15];
    const float* bgS = (const float*)d_in[16];
    const float* gcS = (const float*)d_in[17];
    const float* bcS = (const float*)d_in[18];
    const float* Wout = (const float*)d_in[19];
    const float* bout = (const float*)d_in[20];
    float* out = (float*)d_out;

    float *fh, *fc, *sh, *sc, *z, *zS, *hist;
    cudaGetSymbolAddress((void**)&fh,   g_fh);
    cudaGetSymbolAddress((void**)&fc,   g_fc);
    cudaGetSymbolAddress((void**)&sh,   g_sh);
    cudaGetSymbolAddress((void**)&sc,   g_sc);
    cudaGetSymbolAddress((void**)&z,    g_z);
    cudaGetSymbolAddress((void**)&zS,   g_zS);
    cudaGetSymbolAddress((void**)&hist, g_hist);

    // zero initial states
    {
        int n = B_ * F_;
        init_states<<<(n + 255) / 256, 256>>>();
    }

    const dim3 gF((4 * F_ + 63) / 64, (B_ + 63) / 64);   // N=2800 -> (44,2)
    const dim3 gS4((4 * S_ + 63) / 64, (B_ + 63) / 64);  // N=1600 -> (25,2)

    for (int t = 0; t < T_; t++) {
        // Fast cell 0: x = inputs[:, t, :], h = fh
        gemm_cat<64, 64, 16, 4, 4><<<gF, 256>>>(
            inputs + (size_t)t * E_, T_ * E_, E_,
            fh, F_, F_,
            W0, b0, z, B_, 4 * F_, 4 * F_);
        lstm_pw<<<B_, 256>>>(z, fh, fc, g0, bg0, gc0, bc0, F_, nullptr, 0, 0);

        // Slow cell: x = fh (new), h = sh
        gemm_cat<64, 64, 16, 4, 4><<<gS4, 256>>>(
            fh, F_, F_,
            sh, S_, S_,
            WS, bS, zS, B_, 4 * S_, 4 * S_);
        lstm_pw<<<B_, 256>>>(zS, sh, sc, gS, bgS, gcS, bcS, S_, nullptr, 0, 0);

        // Fast cell 1: x = sh (new), h = fh
        gemm_cat<64, 64, 16, 4, 4><<<gF, 256>>>(
            sh, S_, S_,
            fh, F_, F_,
            W1, b1, z, B_, 4 * F_, 4 * F_);
        lstm_pw<<<B_, 256>>>(z, fh, fc, g1, bg1, gc1, bc1, F_, hist, t, T_);
    }

    // Final projection: logits[b*T+t, :] = hist[b*T+t, :] @ Wout + bout
    {
        const dim3 grid((V_ + 127) / 128, (B_ * T_ + 127) / 128); // (79, 100)
        gemm_cat<128, 128, 8, 8, 8><<<grid, 256>>>(
            hist, F_, F_,
            nullptr, 0, 0,
            Wout, bout, out, B_ * T_, V_, V_);
    }

    // Tail: fh, fc, sh, sc after logits
    {
        int total = 2 * B_ * F_ + 2 * B_ * S_;
        tail_copy<<<(total + 255) / 256, 256>>>(out, (size_t)out_size);
    }
}

// round 7
// speedup vs baseline: 1.8033x; 1.8033x over previous
#include <cuda_runtime.h>
#include <cuda_bf16.h>
#include <cstdint>

// Problem constants
#define B_  128
#define T_  100
#define E_  128
#define F_  700
#define S_  400
#define V_  10000

// Padded leading dims (16B-segment = 8 bf16 alignment everywhere)
#define FH_LDA 720
#define SH_LDA 424
#define HI_LDA 704

typedef __nv_bfloat16 bf16;

// ---------------------------------------------------------------------------
// Static device scratch
// ---------------------------------------------------------------------------
__device__ float g_fh[B_ * F_];
__device__ float g_fc[B_ * F_];
__device__ float g_sh[B_ * S_];
__device__ float g_sc[B_ * S_];
__device__ float g_z [B_ * 4 * F_];
__device__ float g_zS[B_ * 4 * S_];

__device__ bf16 g_xh[B_ * T_ * E_], g_xm[B_ * T_ * E_], g_xl[B_ * T_ * E_];
__device__ bf16 g_fhh[B_ * FH_LDA], g_fhm[B_ * FH_LDA], g_fhl[B_ * FH_LDA];
__device__ bf16 g_shh[B_ * SH_LDA], g_shm[B_ * SH_LDA], g_shl[B_ * SH_LDA];
__device__ bf16 g_hih[(size_t)B_ * T_ * HI_LDA], g_him[(size_t)B_ * T_ * HI_LDA], g_hil[(size_t)B_ * T_ * HI_LDA];

__device__ bf16 g_W0h[(size_t)4 * F_ * 832],  g_W0m[(size_t)4 * F_ * 832],  g_W0l[(size_t)4 * F_ * 832];
__device__ bf16 g_WSh[(size_t)4 * S_ * 1120], g_WSm[(size_t)4 * S_ * 1120], g_WSl[(size_t)4 * S_ * 1120];
__device__ bf16 g_W1h[(size_t)4 * F_ * 1120], g_W1m[(size_t)4 * F_ * 1120], g_W1l[(size_t)4 * F_ * 1120];
__device__ bf16 g_Woh[(size_t)V_ * 704],      g_Wom[(size_t)V_ * 704],      g_Wol[(size_t)V_ * 704];

// ---------------------------------------------------------------------------
// Helpers
// ---------------------------------------------------------------------------
__device__ __forceinline__ uint32_t smem_u32(const void* p) {
    uint32_t a;
    asm("{ .reg .u64 t; cvta.to.shared.u64 t, %1; cvt.u32.u64 %0, t; }" : "=r"(a) : "l"(p));
    return a;
}
__device__ __forceinline__ void split3(float x, bf16& h, bf16& m, bf16& l) {
    h = __float2bfloat16(x);
    float r = x - __bfloat162float(h);
    m = __float2bfloat16(r);
    float r2 = r - __bfloat162float(m);
    l = __float2bfloat16(r2);
}
__device__ __forceinline__ void mma_bf16(float c[4], const uint32_t a[4], const uint32_t b[2]) {
    asm volatile("mma.sync.aligned.m16n8k16.row.col.f32.bf16.bf16.f32 "
                 "{%0,%1,%2,%3}, {%4,%5,%6,%7}, {%8,%9}, {%0,%1,%2,%3};"
                 : "+f"(c[0]), "+f"(c[1]), "+f"(c[2]), "+f"(c[3])
                 : "r"(a[0]), "r"(a[1]), "r"(a[2]), "r"(a[3]), "r"(b[0]), "r"(b[1]));
}
#define CP16(dst, src, sz) \
    asm volatile("cp.async.cg.shared.global [%0], [%1], 16, %2;" \
                 :: "r"(dst), "l"(src), "r"(sz))
#define CP_COMMIT() asm volatile("cp.async.commit_group;" ::: "memory")
#define CP_WAIT1()  asm volatile("cp.async.wait_group 1;" ::: "memory")
#define CP_WAIT0()  asm volatile("cp.async.wait_group 0;" ::: "memory")

// SMEM layout: row pitch 80B = 32 bf16 + pad. A: 3 splits x 2 bufs x 128*80.
#define ARP   80
#define ASZ   (128 * ARP)            // 10240
#define AREG  (6 * ASZ)              // 61440
__device__ __forceinline__ uint32_t a_off(int sp, int buf) { return sp * (2 * ASZ) + buf * ASZ; }

// ---------------------------------------------------------------------------
// bf16 split GEMM: C[M,N] = concat(A1, A2)[M, Kpad] @ Wt[N, Kpad]^T + bias
// PREC == 0: 6 chained products (fast; for the one-shot projection).
// PREC == 1: 9 products; H*H done with C=0 MMA + IEEE FADD register
//            accumulation (removes tensor-core long-chain accumulator error);
//            the 8 products of magnitude <= 2^-8 stay chained in-MMA.
// Block 128 x BN, 8 warps (4m x 2n); BK=32, double-buffered cp.async.
// ---------------------------------------------------------------------------
template <int BN, int PREC>
__global__ void __launch_bounds__(256)
gemm_split(const bf16* __restrict__ A1h, const bf16* __restrict__ A1m, const bf16* __restrict__ A1l,
           long lda1, int K1p,
           const bf16* __restrict__ A2h, const bf16* __restrict__ A2m, const bf16* __restrict__ A2l,
           long lda2,
           const bf16* __restrict__ Wh, const bf16* __restrict__ Wm, const bf16* __restrict__ Wl,
           int ldw,
           const float* __restrict__ bias,
           float* __restrict__ C, long ldc,
           int N, int Kpad)
{
    constexpr int BSZ  = BN * ARP;
    constexpr int WN   = BN / 2;
    constexpr int NT   = WN / 8;
    constexpr int BIT  = 3 * (BN / 64);

    extern __shared__ char sm[];
    const uint32_t sbase = smem_u32(sm);

    const int tid  = threadIdx.x;
    const int wid  = tid >> 5;
    const int lane = tid & 31;
    const int wm   = wid & 3;
    const int wn   = wid >> 2;
    const int n0   = blockIdx.x * BN;
    const long m0  = (long)blockIdx.y * 128;
    const int nk   = Kpad >> 5;

    const bf16* A1s[3] = {A1h, A1m, A1l};
    const bf16* A2s[3] = {A2h, A2m, A2l};
    const bf16* Ws [3] = {Wh,  Wm,  Wl};

    float acc[2][NT][4];        // PREC1: big (H*H, IEEE chain); PREC0: everything
    float accs[PREC ? 2 : 1][PREC ? NT : 1][4];   // PREC1: small products
    #pragma unroll
    for (int mt = 0; mt < 2; mt++)
        #pragma unroll
        for (int nt = 0; nt < NT; nt++)
            #pragma unroll
            for (int r = 0; r < 4; r++) {
                acc[mt][nt][r] = 0.0f;
                if (PREC) accs[mt][nt][r] = 0.0f;
            }

    auto load_chunk = [&](int i) {
        const int k0 = i << 5;
        const int buf = i & 1;
        #pragma unroll
        for (int it = 0; it < 6; it++) {
            const int sp  = it >> 1;
            const int idx = ((it & 1) << 8) + tid;
            const int r   = idx >> 2;
            const int c4  = idx & 3;
            const int gk  = k0 + (c4 << 3);
            const bf16* src = (gk < K1p) ? A1s[sp] + (m0 + r) * lda1 + gk
                                         : A2s[sp] + (m0 + r) * lda2 + (gk - K1p);
            CP16(sbase + a_off(sp, buf) + r * ARP + c4 * 16, src, 16);
        }
        #pragma unroll
        for (int it = 0; it < BIT; it++) {
            const int sp  = (BN == 64) ? it : (it >> 1);
            const int idx = (BN == 64) ? tid : (((it & 1) << 8) + tid);
            const int r   = idx >> 2;
            const int c4  = idx & 3;
            const int n   = n0 + r;
            const int nc  = (n < N) ? n : (N - 1);
            const bf16* src = Ws[sp] + (long)nc * ldw + k0 + (c4 << 3);
            CP16(sbase + AREG + sp * (2 * BSZ) + buf * BSZ + r * ARP + c4 * 16,
                 src, (n < N) ? 16 : 0);
        }
        CP_COMMIT();
    };

    load_chunk(0);
    for (int i = 0; i < nk; i++) {
        if (i + 1 < nk) { load_chunk(i + 1); CP_WAIT1(); }
        else            { CP_WAIT0(); }
        __syncthreads();
        const int buf = i & 1;

        #pragma unroll
        for (int ks = 0; ks < 2; ks++) {
            const uint32_t kb = (ks << 5) + ((lane & 3) << 2);
            uint32_t a[3][2][4];
            #pragma unroll
            for (int sp = 0; sp < 3; sp++)
                #pragma unroll
                for (int mt = 0; mt < 2; mt++) {
                    const char* base = sm + a_off(sp, buf)
                                     + (wm * 32 + mt * 16 + (lane >> 2)) * ARP + kb;
                    a[sp][mt][0] = *(const uint32_t*)(base);
                    a[sp][mt][1] = *(const uint32_t*)(base + 8 * ARP);
                    a[sp][mt][2] = *(const uint32_t*)(base + 16);
                    a[sp][mt][3] = *(const uint32_t*)(base + 8 * ARP + 16);
                }
            uint32_t b[3][NT][2];
            #pragma unroll
            for (int sp = 0; sp < 3; sp++)
                #pragma unroll
                for (int nt = 0; nt < NT; nt++) {
                    const char* base = sm + AREG + sp * (2 * BSZ) + buf * BSZ
                                     + (wn * WN + nt * 8 + (lane >> 2)) * ARP + kb;
                    b[sp][nt][0] = *(const uint32_t*)(base);
                    b[sp][nt][1] = *(const uint32_t*)(base + 16);
                }
            #pragma unroll
            for (int mt = 0; mt < 2; mt++)
                #pragma unroll
                for (int nt = 0; nt < NT; nt++) {
                    if (PREC) {
                        // 8 small products chained in-MMA (|.| <= 2^-8)
                        mma_bf16(accs[mt][nt], a[2][mt], b[2][nt]);  // L*L
                        mma_bf16(accs[mt][nt], a[2][mt], b[1][nt]);  // L*M
                        mma_bf16(accs[mt][nt], a[1][mt], b[2][nt]);  // M*L
                        mma_bf16(accs[mt][nt], a[2][mt], b[0][nt]);  // L*H
                        mma_bf16(accs[mt][nt], a[1][mt], b[1][nt]);  // M*M
                        mma_bf16(accs[mt][nt], a[0][mt], b[2][nt]);  // H*L
                        mma_bf16(accs[mt][nt], a[1][mt], b[0][nt]);  // M*H
                        mma_bf16(accs[mt][nt], a[0][mt], b[1][nt]);  // H*M
                        // H*H: zero-C MMA, IEEE FADD into register chain
                        float d[4] = {0.f, 0.f, 0.f, 0.f};
                        mma_bf16(d, a[0][mt], b[0][nt]);
                        acc[mt][nt][0] += d[0];
                        acc[mt][nt][1] += d[1];
                        acc[mt][nt][2] += d[2];
                        acc[mt][nt][3] += d[3];
                    } else {
                        mma_bf16(acc[mt][nt], a[0][mt], b[2][nt]);  // H*L
                        mma_bf16(acc[mt][nt], a[1][mt], b[1][nt]);  // M*M
                        mma_bf16(acc[mt][nt], a[2][mt], b[0][nt]);  // L*H
                        mma_bf16(acc[mt][nt], a[0][mt], b[1][nt]);  // H*M
                        mma_bf16(acc[mt][nt], a[1][mt], b[0][nt]);  // M*H
                        mma_bf16(acc[mt][nt], a[0][mt], b[0][nt]);  // H*H
                    }
                }
        }
        __syncthreads();
    }

    // epilogue: bias + store
    #pragma unroll
    for (int mt = 0; mt < 2; mt++) {
        long gm = m0 + wm * 32 + mt * 16 + (lane >> 2);
        #pragma unroll
        for (int nt = 0; nt < NT; nt++) {
            int gn = n0 + wn * WN + nt * 8 + ((lane & 3) << 1);
            if (gn < N) {
                float2 bv = *(const float2*)(bias + gn);
                float r0 = acc[mt][nt][0], r1 = acc[mt][nt][1];
                float r2 = acc[mt][nt][2], r3 = acc[mt][nt][3];
                if (PREC) {
                    r0 += accs[mt][nt][0]; r1 += accs[mt][nt][1];
                    r2 += accs[mt][nt][2]; r3 += accs[mt][nt][3];
                }
                float2 o0 = make_float2(r0 + bv.x, r1 + bv.y);
                float2 o1 = make_float2(r2 + bv.x, r3 + bv.y);
                *(float2*)(C + gm * ldc + gn)       = o0;
                *(float2*)(C + (gm + 8) * ldc + gn) = o1;
            }
        }
    }
}

// ---------------------------------------------------------------------------
// Weight transpose + pad + split
// ---------------------------------------------------------------------------
__global__ void transpose_split(const float* __restrict__ in,
                                bf16* __restrict__ oh, bf16* __restrict__ om, bf16* __restrict__ ol,
                                int N, int ldw, int K1, int gap, int Ktot)
{
    long idx = (long)blockIdx.x * blockDim.x + threadIdx.x;
    long total = (long)N * ldw;
    if (idx >= total) return;
    int n = (int)(idx / ldw);
    int k = (int)(idx % ldw);
    float v = 0.0f;
    if (k < K1)                        v = in[(long)k * N + n];
    else if (k >= K1 + gap && k < Ktot + gap) v = in[(long)(k - gap) * N + n];
    bf16 h, m, l;
    split3(v, h, m, l);
    oh[idx] = h; om[idx] = m; ol[idx] = l;
}

__global__ void split_inputs(const float* __restrict__ in)
{
    long idx = (long)blockIdx.x * blockDim.x + threadIdx.x;
    if (idx >= (long)B_ * T_ * E_) return;
    bf16 h, m, l;
    split3(in[idx], h, m, l);
    g_xh[idx] = h; g_xm[idx] = m; g_xl[idx] = l;
}

// ---------------------------------------------------------------------------
// Fused LN-LSTM pointwise
// ---------------------------------------------------------------------------
__device__ __forceinline__ float sigm(float x) { return 1.0f / (1.0f + __expf(-x)); }

__device__ __forceinline__ float blockReduceSum(float v, float* red) {
    int lane = threadIdx.x & 31;
    int w    = threadIdx.x >> 5;
    #pragma unroll
    for (int o = 16; o > 0; o >>= 1) v += __shfl_down_sync(0xffffffffu, v, o);
    if (lane == 0) red[w] = v;
    __syncthreads();
    float r = 0.0f;
    if (w == 0) {
        int nw = blockDim.x >> 5;
        r = (lane < nw) ? red[lane] : 0.0f;
        #pragma unroll
        for (int o = 16; o > 0; o >>= 1) r += __shfl_down_sync(0xffffffffu, r, o);
        if (lane == 0) red[0] = r;
    }
    __syncthreads();
    r = red[0];
    __syncthreads();
    return r;
}

__global__ void __launch_bounds__(256)
lstm_pw(const float* __restrict__ z,
        float* __restrict__ h, float* __restrict__ c, int H,
        const float* __restrict__ gg, const float* __restrict__ bg,
        const float* __restrict__ gc, const float* __restrict__ bc,
        bf16* __restrict__ sph, bf16* __restrict__ spm, bf16* __restrict__ spl, int sp_lda,
        bf16* __restrict__ hih, bf16* __restrict__ him, bf16* __restrict__ hil, int t)
{
    const int b = blockIdx.x;
    const float* zb = z + (size_t)b * 4 * H;
    __shared__ float red[32];
    const float invH = 1.0f / (float)H;

    float s[4] = {0, 0, 0, 0}, q[4] = {0, 0, 0, 0};
    for (int u = threadIdx.x; u < H; u += blockDim.x) {
        #pragma unroll
        for (int ch = 0; ch < 4; ch++) {
            float v = zb[ch * H + u];
            s[ch] += v;
            q[ch] += v * v;
        }
    }
    float mu[4], rs[4];
    #pragma unroll
    for (int ch = 0; ch < 4; ch++) {
        float smv = blockReduceSum(s[ch], red);
        float sq  = blockReduceSum(q[ch], red);
        mu[ch] = smv * invH;
        float var = sq * invH - mu[ch] * mu[ch];
        rs[ch] = rsqrtf(var + 1e-5f);
    }

    float nc_r[3], so_r[3];
    float sc_acc = 0.0f, qc_acc = 0.0f;
    #pragma unroll
    for (int it = 0; it < 3; it++) {
        int u = threadIdx.x + it * 256;
        if (u < H) {
            float iv = (zb[0 * H + u] - mu[0]) * rs[0] * gg[0 * H + u] + bg[0 * H + u];
            float jv = (zb[1 * H + u] - mu[1]) * rs[1] * gg[1 * H + u] + bg[1 * H + u];
            float fv = (zb[2 * H + u] - mu[2]) * rs[2] * gg[2 * H + u] + bg[2 * H + u];
            float ov = (zb[3 * H + u] - mu[3]) * rs[3] * gg[3 * H + u] + bg[3 * H + u];
            float cold = c[(size_t)b * H + u];
            float nc = cold * sigm(fv + 1.0f) + sigm(iv) * tanhf(jv);
            nc_r[it] = nc;
            so_r[it] = sigm(ov);
            sc_acc += nc;
            qc_acc += nc * nc;
        }
    }
    float smc = blockReduceSum(sc_acc, red);
    float sqc = blockReduceSum(qc_acc, red);
    float muc = smc * invH;
    float rsc = rsqrtf(sqc * invH - muc * muc + 1e-5f);

    #pragma unroll
    for (int it = 0; it < 3; it++) {
        int u = threadIdx.x + it * 256;
        if (u < H) {
            float nc = nc_r[it];
            float nh = tanhf((nc - muc) * rsc * gc[u] + bc[u]) * so_r[it];
            float hold = h[(size_t)b * H + u];
            float cold = c[(size_t)b * H + u];
            float hn = 0.9f * nh + 0.1f * hold;
            float cn = 0.5f * nc + 0.5f * cold;
            h[(size_t)b * H + u] = hn;
            c[(size_t)b * H + u] = cn;
            bf16 sh_, sm_, sl_;
            split3(hn, sh_, sm_, sl_);
            size_t so = (size_t)b * sp_lda + u;
            sph[so] = sh_; spm[so] = sm_; spl[so] = sl_;
            if (hih) {
                size_t ho = ((size_t)b * T_ + t) * HI_LDA + u;
                hih[ho] = sh_; him[ho] = sm_; hil[ho] = sl_;
            }
        }
    }
}

// ---------------------------------------------------------------------------
// Init + tail copy
// ---------------------------------------------------------------------------
__global__ void init_states()
{
    int i = blockIdx.x * blockDim.x + threadIdx.x;
    int stride = gridDim.x * blockDim.x;
    const bf16 bz = __float2bfloat16(0.0f);
    for (int j = i; j < B_ * F_; j += stride) { g_fh[j] = 0.0f; g_fc[j] = 0.0f; }
    for (int j = i; j < B_ * S_; j += stride) { g_sh[j] = 0.0f; g_sc[j] = 0.0f; }
    for (int j = i; j < B_ * FH_LDA; j += stride) { g_fhh[j] = bz; g_fhm[j] = bz; g_fhl[j] = bz; }
    for (int j = i; j < B_ * SH_LDA; j += stride) { g_shh[j] = bz; g_shm[j] = bz; g_shl[j] = bz; }
    for (int j = i; j < B_ * T_ * 4; j += stride) {
        size_t off = (size_t)(j >> 2) * HI_LDA + F_ + (j & 3);
        g_hih[off] = bz; g_him[off] = bz; g_hil[off] = bz;
    }
}

__global__ void tail_copy(float* __restrict__ out, size_t out_total)
{
    int i = blockIdx.x * blockDim.x + threadIdx.x;
    const size_t base = (size_t)B_ * T_ * V_;
    const int nF = B_ * F_, nS = B_ * S_;
    const int total = 2 * nF + 2 * nS;
    if (i >= total) return;
    float v;
    size_t off = base + i;
    if (i < nF)               v = g_fh[i];
    else if (i < 2 * nF)      v = g_fc[i - nF];
    else if (i < 2 * nF + nS) v = g_sh[i - 2 * nF];
    else                      v = g_sc[i - 2 * nF - nS];
    if (off < out_total) out[off] = v;
}

// ---------------------------------------------------------------------------
// Launch
// ---------------------------------------------------------------------------
extern "C" void kernel_launch(void* const* d_in, const int* in_sizes, int n_in,
                              void* d_out, int out_size)
{
    const float* inputs = (const float*)d_in[0];
    const float* W0  = (const float*)d_in[1];
    const float* b0  = (const float*)d_in[2];
    const float* g0  = (const float*)d_in[3];
    const float* bg0 = (const float*)d_in[4];
    const float* gc0 = (const float*)d_in[5];
    const float* bc0 = (const float*)d_in[6];
    const float* W1  = (const float*)d_in[7];
    const float* b1  = (const float*)d_in[8];
    const float* g1  = (const float*)d_in[9];
    const float* bg1 = (const float*)d_in[10];
    const float* gc1 = (const float*)d_in[11];
    const float* bc1 = (const float*)d_in[12];
    const float* WS  = (const float*)d_in[13];
    const float* bS  = (const float*)d_in[14];
    const float* gS  = (const float*)d_in[15];
    const float* bgS = (const float*)d_in[16];
    const float* gcS = (const float*)d_in[17];
    const float* bcS = (const float*)d_in[18];
    const float* Wout = (const float*)d_in[19];
    const float* bout = (const float*)d_in[20];
    float* out = (float*)d_out;

    float *fh, *fc, *sh, *sc, *z, *zS;
    bf16 *xh, *xm, *xl, *fhh, *fhm, *fhl, *shh, *shm, *shl, *hih, *him, *hil;
    bf16 *W0h, *W0m, *W0l, *WSh, *WSm, *WSl, *W1h, *W1m, *W1l, *Woh, *Wom, *Wol;
    cudaGetSymbolAddress((void**)&fh,  g_fh);  cudaGetSymbolAddress((void**)&fc,  g_fc);
    cudaGetSymbolAddress((void**)&sh,  g_sh);  cudaGetSymbolAddress((void**)&sc,  g_sc);
    cudaGetSymbolAddress((void**)&z,   g_z);   cudaGetSymbolAddress((void**)&zS,  g_zS);
    cudaGetSymbolAddress((void**)&xh,  g_xh);  cudaGetSymbolAddress((void**)&xm,  g_xm);  cudaGetSymbolAddress((void**)&xl,  g_xl);
    cudaGetSymbolAddress((void**)&fhh, g_fhh); cudaGetSymbolAddress((void**)&fhm, g_fhm); cudaGetSymbolAddress((void**)&fhl, g_fhl);
    cudaGetSymbolAddress((void**)&shh, g_shh); cudaGetSymbolAddress((void**)&shm, g_shm); cudaGetSymbolAddress((void**)&shl, g_shl);
    cudaGetSymbolAddress((void**)&hih, g_hih); cudaGetSymbolAddress((void**)&him, g_him); cudaGetSymbolAddress((void**)&hil, g_hil);
    cudaGetSymbolAddress((void**)&W0h, g_W0h); cudaGetSymbolAddress((void**)&W0m, g_W0m); cudaGetSymbolAddress((void**)&W0l, g_W0l);
    cudaGetSymbolAddress((void**)&WSh, g_WSh); cudaGetSymbolAddress((void**)&WSm, g_WSm); cudaGetSymbolAddress((void**)&WSl, g_WSl);
    cudaGetSymbolAddress((void**)&W1h, g_W1h); cudaGetSymbolAddress((void**)&W1m, g_W1m); cudaGetSymbolAddress((void**)&W1l, g_W1l);
    cudaGetSymbolAddress((void**)&Woh, g_Woh); cudaGetSymbolAddress((void**)&Wom, g_Wom); cudaGetSymbolAddress((void**)&Wol, g_Wol);

    const int SM64  = AREG + 6 * 64 * ARP;    // 92160
    const int SM128 = AREG + 6 * 128 * ARP;   // 122880
    cudaFuncSetAttribute(gemm_split<64, 1>,  cudaFuncAttributeMaxDynamicSharedMemorySize, SM64);
    cudaFuncSetAttribute(gemm_split<128, 0>, cudaFuncAttributeMaxDynamicSharedMemorySize, SM128);

    // Weight transpose + split
    {
        long n;
        n = (long)4 * F_ * 832;
        transpose_split<<<(unsigned)((n + 255) / 256), 256>>>(W0, W0h, W0m, W0l, 4 * F_, 832, 828, 0, 828);
        n = (long)4 * S_ * 1120;
        transpose_split<<<(unsigned)((n + 255) / 256), 256>>>(WS, WSh, WSm, WSl, 4 * S_, 1120, 700, 4, 1100);
        n = (long)4 * F_ * 1120;
        transpose_split<<<(unsigned)((n + 255) / 256), 256>>>(W1, W1h, W1m, W1l, 4 * F_, 1120, 1100, 0, 1100);
        n = (long)V_ * 704;
        transpose_split<<<(unsigned)((n + 255) / 256), 256>>>(Wout, Woh, Wom, Wol, V_, 704, 700, 0, 700);
    }
    {
        long n = (long)B_ * T_ * E_;
        split_inputs<<<(unsigned)((n + 255) / 256), 256>>>(inputs);
    }
    init_states<<<148, 256>>>();

    const dim3 gC((4 * F_ + 63) / 64, 1);   // 44 CTAs, N=2800
    const dim3 gSl((4 * S_ + 63) / 64, 1);  // 25 CTAs, N=1600

    for (int t = 0; t < T_; t++) {
        // Fast cell 0: A = [x_t | fh], Kpad=832, K1p=128
        gemm_split<64, 1><<<gC, 256, SM64>>>(
            xh + (size_t)t * E_, xm + (size_t)t * E_, xl + (size_t)t * E_, (long)T_ * E_, 128,
            fhh, fhm, fhl, FH_LDA,
            W0h, W0m, W0l, 832, b0, z, 4 * F_, 4 * F_, 832);
        lstm_pw<<<B_, 256>>>(z, fh, fc, F_, g0, bg0, gc0, bc0,
                             fhh, fhm, fhl, FH_LDA, nullptr, nullptr, nullptr, 0);

        // Slow cell: A = [fh | gap4 | sh], Kpad=1120, K1p=704
        gemm_split<64, 1><<<gSl, 256, SM64>>>(
            fhh, fhm, fhl, FH_LDA, 704,
            shh, shm, shl, SH_LDA,
            WSh, WSm, WSl, 1120, bS, zS, 4 * S_, 4 * S_, 1120);
        lstm_pw<<<B_, 256>>>(zS, sh, sc, S_, gS, bgS, gcS, bcS,
                             shh, shm, shl, SH_LDA, nullptr, nullptr, nullptr, 0);

        // Fast cell 1: A = [sh | fh], Kpad=1120, K1p=400
        gemm_split<64, 1><<<gC, 256, SM64>>>(
            shh, shm, shl, SH_LDA, 400,
            fhh, fhm, fhl, FH_LDA,
            W1h, W1m, W1l, 1120, b1, z, 4 * F_, 4 * F_, 1120);
        lstm_pw<<<B_, 256>>>(z, fh, fc, F_, g1, bg1, gc1, bc1,
                             fhh, fhm, fhl, FH_LDA, hih, him, hil, t);
    }

    // Output projection: hist[12800, 704] @ WoutT[10000, 704]^T
    {
        const dim3 grid((V_ + 127) / 128, (B_ * T_) / 128);   // 79 x 100
        gemm_split<128, 0><<<grid, 256, SM128>>>(
            hih, him, hil, HI_LDA, 704,
            hih, him, hil, HI_LDA,
            Woh, Wom, Wol, 704, bout, out, V_, V_, 704);
    }

    {
        int total = 2 * B_ * F_ + 2 * B_ * S_;
        tail_copy<<<(total + 255) / 256, 256>>>(out, (size_t)out_size);
    }
}

// round 8
// speedup vs baseline: 4.2415x; 2.3521x over previous
#include <cuda_runtime.h>
#include <cuda_bf16.h>
#include <cstdint>

// Problem constants
#define B_  128
#define T_  100
#define E_  128
#define F_  700
#define S_  400
#define V_  10000

#define FH_LDA 720
#define SH_LDA 424
#define HI_LDA 704

#define KS_CELL 3
#define KS_SLOW 5

typedef __nv_bfloat16 bf16;

// ---------------------------------------------------------------------------
// Static device scratch
// ---------------------------------------------------------------------------
__device__ float g_fh[B_ * F_];
__device__ float g_fc[B_ * F_];
__device__ float g_sh[B_ * S_];
__device__ float g_sc[B_ * S_];
__device__ float g_z [KS_CELL * B_ * 4 * F_];   // split-K partials (cell cells)
__device__ float g_zS[KS_SLOW * B_ * 4 * S_];   // split-K partials (slow cell)

__device__ bf16 g_xh[B_ * T_ * E_], g_xm[B_ * T_ * E_], g_xl[B_ * T_ * E_];
__device__ bf16 g_fhh[B_ * FH_LDA], g_fhm[B_ * FH_LDA], g_fhl[B_ * FH_LDA];
__device__ bf16 g_shh[B_ * SH_LDA], g_shm[B_ * SH_LDA], g_shl[B_ * SH_LDA];
__device__ bf16 g_hih[(size_t)B_ * T_ * HI_LDA], g_him[(size_t)B_ * T_ * HI_LDA], g_hil[(size_t)B_ * T_ * HI_LDA];

__device__ bf16 g_W0h[(size_t)4 * F_ * 832],  g_W0m[(size_t)4 * F_ * 832],  g_W0l[(size_t)4 * F_ * 832];
__device__ bf16 g_WSh[(size_t)4 * S_ * 1120], g_WSm[(size_t)4 * S_ * 1120], g_WSl[(size_t)4 * S_ * 1120];
__device__ bf16 g_W1h[(size_t)4 * F_ * 1120], g_W1m[(size_t)4 * F_ * 1120], g_W1l[(size_t)4 * F_ * 1120];
__device__ bf16 g_Woh[(size_t)V_ * 704],      g_Wom[(size_t)V_ * 704],      g_Wol[(size_t)V_ * 704];

// ---------------------------------------------------------------------------
// Helpers
// ---------------------------------------------------------------------------
__device__ __forceinline__ uint32_t smem_u32(const void* p) {
    uint32_t a;
    asm("{ .reg .u64 t; cvta.to.shared.u64 t, %1; cvt.u32.u64 %0, t; }" : "=r"(a) : "l"(p));
    return a;
}
__device__ __forceinline__ void split3(float x, bf16& h, bf16& m, bf16& l) {
    h = __float2bfloat16(x);
    float r = x - __bfloat162float(h);
    m = __float2bfloat16(r);
    float r2 = r - __bfloat162float(m);
    l = __float2bfloat16(r2);
}
__device__ __forceinline__ void mma_bf16(float c[4], const uint32_t a[4], const uint32_t b[2]) {
    asm volatile("mma.sync.aligned.m16n8k16.row.col.f32.bf16.bf16.f32 "
                 "{%0,%1,%2,%3}, {%4,%5,%6,%7}, {%8,%9}, {%0,%1,%2,%3};"
                 : "+f"(c[0]), "+f"(c[1]), "+f"(c[2]), "+f"(c[3])
                 : "r"(a[0]), "r"(a[1]), "r"(a[2]), "r"(a[3]), "r"(b[0]), "r"(b[1]));
}
#define CP16(dst, src, sz) \
    asm volatile("cp.async.cg.shared.global [%0], [%1], 16, %2;" \
                 :: "r"(dst), "l"(src), "r"(sz))
#define CP_COMMIT() asm volatile("cp.async.commit_group;" ::: "memory")
#define CP_WAIT1()  asm volatile("cp.async.wait_group 1;" ::: "memory")
#define CP_WAIT0()  asm volatile("cp.async.wait_group 0;" ::: "memory")

#define ARP   80
#define ASZ   (128 * ARP)            // 10240 bytes per A split-buffer

// ---------------------------------------------------------------------------
// bf16-split GEMM.
//  MODE 1 (recurrence): 3 splits, 6 products, H*H via zero-C MMA + IEEE FADD.
//     Split-K over gridDim.z; writes raw partials (no bias) at z-offset.
//  MODE 2 (projection): 2 splits (h,m), 3 chained products, bias added.
// Block 128 x BN, 8 warps (4m x 2n); BK=32, double-buffered cp.async.
// ---------------------------------------------------------------------------
template <int BN, int MODE>
__global__ void __launch_bounds__(256)
gemm_split(const bf16* __restrict__ A1h, const bf16* __restrict__ A1m, const bf16* __restrict__ A1l,
           long lda1, int K1p,
           const bf16* __restrict__ A2h, const bf16* __restrict__ A2m, const bf16* __restrict__ A2l,
           long lda2,
           const bf16* __restrict__ Wh, const bf16* __restrict__ Wm, const bf16* __restrict__ Wl,
           int ldw,
           const float* __restrict__ bias,
           float* __restrict__ C, long ldc, size_t pstride,
           int N, int Kpad)
{
    constexpr int NSP   = (MODE == 2) ? 2 : 3;
    constexpr int BSZ   = BN * ARP;
    constexpr int WN    = BN / 2;
    constexpr int NT    = WN / 8;
    constexpr int BHALF = BN / 64;
    constexpr uint32_t BBASE = NSP * 2 * ASZ;

    extern __shared__ char sm[];
    const uint32_t sbase = smem_u32(sm);

    const int tid  = threadIdx.x;
    const int wid  = tid >> 5;
    const int lane = tid & 31;
    const int wm   = wid & 3;
    const int wn   = wid >> 2;
    const int n0   = blockIdx.x * BN;
    const long m0  = (long)blockIdx.y * 128;
    const int nk   = Kpad >> 5;

    // split-K range
    const int KS  = gridDim.z;
    const int kz  = blockIdx.z;
    const int nkq = (nk + KS - 1) / KS;
    const int i0  = kz * nkq;
    const int i1  = (i0 + nkq < nk) ? (i0 + nkq) : nk;

    const bf16* A1s[3] = {A1h, A1m, A1l};
    const bf16* A2s[3] = {A2h, A2m, A2l};
    const bf16* Ws [3] = {Wh,  Wm,  Wl};

    float acc[2][NT][4];
    float accs[MODE == 1 ? 2 : 1][MODE == 1 ? NT : 1][4];
    #pragma unroll
    for (int mt = 0; mt < 2; mt++)
        #pragma unroll
        for (int nt = 0; nt < NT; nt++)
            #pragma unroll
            for (int r = 0; r < 4; r++) {
                acc[mt][nt][r] = 0.0f;
                if (MODE == 1) accs[mt][nt][r] = 0.0f;
            }

    auto load_chunk = [&](int i) {
        const int k0 = i << 5;
        const int buf = i & 1;
        #pragma unroll
        for (int it = 0; it < NSP * 2; it++) {
            const int sp  = it >> 1;
            const int idx = ((it & 1) << 8) + tid;
            const int r   = idx >> 2;
            const int c4  = idx & 3;
            const int gk  = k0 + (c4 << 3);
            const bf16* src = (gk < K1p) ? A1s[sp] + (m0 + r) * lda1 + gk
                                         : A2s[sp] + (m0 + r) * lda2 + (gk - K1p);
            CP16(sbase + sp * (2 * ASZ) + buf * ASZ + r * ARP + c4 * 16, src, 16);
        }
        #pragma unroll
        for (int it = 0; it < NSP * BHALF; it++) {
            const int sp  = it / BHALF;
            const int idx = ((it % BHALF) << 8) + tid;
            const int r   = idx >> 2;
            const int c4  = idx & 3;
            const int n   = n0 + r;
            const int nc  = (n < N) ? n : (N - 1);
            const bf16* src = Ws[sp] + (long)nc * ldw + k0 + (c4 << 3);
            CP16(sbase + BBASE + sp * (2 * BSZ) + buf * BSZ + r * ARP + c4 * 16,
                 src, (n < N) ? 16 : 0);
        }
        CP_COMMIT();
    };

    if (i0 < i1) load_chunk(i0);
    for (int i = i0; i < i1; i++) {
        if (i + 1 < i1) { load_chunk(i + 1); CP_WAIT1(); }
        else            { CP_WAIT0(); }
        __syncthreads();
        const int buf = i & 1;

        #pragma unroll
        for (int ks = 0; ks < 2; ks++) {
            const uint32_t kb = (ks << 5) + ((lane & 3) << 2);
            uint32_t a[NSP][2][4];
            #pragma unroll
            for (int sp = 0; sp < NSP; sp++)
                #pragma unroll
                for (int mt = 0; mt < 2; mt++) {
                    const char* base = sm + sp * (2 * ASZ) + buf * ASZ
                                     + (wm * 32 + mt * 16 + (lane >> 2)) * ARP + kb;
                    a[sp][mt][0] = *(const uint32_t*)(base);
                    a[sp][mt][1] = *(const uint32_t*)(base + 8 * ARP);
                    a[sp][mt][2] = *(const uint32_t*)(base + 16);
                    a[sp][mt][3] = *(const uint32_t*)(base + 8 * ARP + 16);
                }
            uint32_t b[NSP][NT][2];
            #pragma unroll
            for (int sp = 0; sp < NSP; sp++)
                #pragma unroll
                for (int nt = 0; nt < NT; nt++) {
                    const char* base = sm + BBASE + sp * (2 * BSZ) + buf * BSZ
                                     + (wn * WN + nt * 8 + (lane >> 2)) * ARP + kb;
                    b[sp][nt][0] = *(const uint32_t*)(base);
                    b[sp][nt][1] = *(const uint32_t*)(base + 16);
                }
            #pragma unroll
            for (int mt = 0; mt < 2; mt++)
                #pragma unroll
                for (int nt = 0; nt < NT; nt++) {
                    if (MODE == 1) {
                        // 5 small products chained in-MMA (|.| <= 2^-8)
                        mma_bf16(accs[mt][nt], a[0][mt], b[2][nt]);  // H*L
                        mma_bf16(accs[mt][nt], a[1][mt], b[1][nt]);  // M*M
                        mma_bf16(accs[mt][nt], a[2][mt], b[0][nt]);  // L*H
                        mma_bf16(accs[mt][nt], a[0][mt], b[1][nt]);  // H*M
                        mma_bf16(accs[mt][nt], a[1][mt], b[0][nt]);  // M*H
                        // H*H: zero-C MMA + IEEE FADD register chain
                        float d[4] = {0.f, 0.f, 0.f, 0.f};
                        mma_bf16(d, a[0][mt], b[0][nt]);
                        acc[mt][nt][0] += d[0];
                        acc[mt][nt][1] += d[1];
                        acc[mt][nt][2] += d[2];
                        acc[mt][nt][3] += d[3];
                    } else {
                        mma_bf16(acc[mt][nt], a[0][mt], b[1][nt]);  // H*M
                        mma_bf16(acc[mt][nt], a[1][mt], b[0][nt]);  // M*H
                        mma_bf16(acc[mt][nt], a[0][mt], b[0][nt]);  // H*H
                    }
                }
        }
        __syncthreads();
    }

    // epilogue
    float* Cp = C + (size_t)kz * pstride;
    #pragma unroll
    for (int mt = 0; mt < 2; mt++) {
        long gm = m0 + wm * 32 + mt * 16 + (lane >> 2);
        #pragma unroll
        for (int nt = 0; nt < NT; nt++) {
            int gn = n0 + wn * WN + nt * 8 + ((lane & 3) << 1);
            if (gn < N) {
                float r0 = acc[mt][nt][0], r1 = acc[mt][nt][1];
                float r2 = acc[mt][nt][2], r3 = acc[mt][nt][3];
                if (MODE == 1) {
                    r0 += accs[mt][nt][0]; r1 += accs[mt][nt][1];
                    r2 += accs[mt][nt][2]; r3 += accs[mt][nt][3];
                }
                if (bias) {
                    float2 bv = *(const float2*)(bias + gn);
                    r0 += bv.x; r1 += bv.y; r2 += bv.x; r3 += bv.y;
                }
                *(float2*)(Cp + gm * ldc + gn)       = make_float2(r0, r1);
                *(float2*)(Cp + (gm + 8) * ldc + gn) = make_float2(r2, r3);
            }
        }
    }
}

// ---------------------------------------------------------------------------
// Weight transpose + pad + split
// ---------------------------------------------------------------------------
__global__ void transpose_split(const float* __restrict__ in,
                                bf16* __restrict__ oh, bf16* __restrict__ om, bf16* __restrict__ ol,
                                int N, int ldw, int K1, int gap, int Ktot)
{
    long idx = (long)blockIdx.x * blockDim.x + threadIdx.x;
    long total = (long)N * ldw;
    if (idx >= total) return;
    int n = (int)(idx / ldw);
    int k = (int)(idx % ldw);
    float v = 0.0f;
    if (k < K1)                               v = in[(long)k * N + n];
    else if (k >= K1 + gap && k < Ktot + gap) v = in[(long)(k - gap) * N + n];
    bf16 h, m, l;
    split3(v, h, m, l);
    oh[idx] = h; om[idx] = m; ol[idx] = l;
}

__global__ void split_inputs(const float* __restrict__ in)
{
    long idx = (long)blockIdx.x * blockDim.x + threadIdx.x;
    if (idx >= (long)B_ * T_ * E_) return;
    bf16 h, m, l;
    split3(in[idx], h, m, l);
    g_xh[idx] = h; g_xm[idx] = m; g_xl[idx] = l;
}

// ---------------------------------------------------------------------------
// Fused LN-LSTM pointwise; sums split-K partials + bias into smem first.
// ---------------------------------------------------------------------------
__device__ __forceinline__ float sigm(float x) { return 1.0f / (1.0f + __expf(-x)); }

__device__ __forceinline__ float blockReduceSum(float v, float* red) {
    int lane = threadIdx.x & 31;
    int w    = threadIdx.x >> 5;
    #pragma unroll
    for (int o = 16; o > 0; o >>= 1) v += __shfl_down_sync(0xffffffffu, v, o);
    if (lane == 0) red[w] = v;
    __syncthreads();
    float r = 0.0f;
    if (w == 0) {
        int nw = blockDim.x >> 5;
        r = (lane < nw) ? red[lane] : 0.0f;
        #pragma unroll
        for (int o = 16; o > 0; o >>= 1) r += __shfl_down_sync(0xffffffffu, r, o);
        if (lane == 0) red[0] = r;
    }
    __syncthreads();
    r = red[0];
    __syncthreads();
    return r;
}

__global__ void __launch_bounds__(256)
lstm_pw(const float* __restrict__ zp, size_t pstride, int nparts,
        const float* __restrict__ bias,
        float* __restrict__ h, float* __restrict__ c, int H,
        const float* __restrict__ gg, const float* __restrict__ bg,
        const float* __restrict__ gc, const float* __restrict__ bc,
        bf16* __restrict__ sph, bf16* __restrict__ spm, bf16* __restrict__ spl, int sp_lda,
        bf16* __restrict__ hih, bf16* __restrict__ him, bf16* __restrict__ hil, int t)
{
    const int b = blockIdx.x;
    __shared__ float zs[4 * F_];
    __shared__ float red[32];
    const float invH = 1.0f / (float)H;
    const size_t rowoff = (size_t)b * 4 * H;

    // Sum split-K partials + bias into smem; accumulate per-chunk stats.
    float s[4] = {0, 0, 0, 0}, q[4] = {0, 0, 0, 0};
    for (int u = threadIdx.x; u < H; u += blockDim.x) {
        #pragma unroll
        for (int ch = 0; ch < 4; ch++) {
            const int off = ch * H + u;
            float v = bias[off];
            for (int p = 0; p < nparts; p++)
                v += zp[(size_t)p * pstride + rowoff + off];
            zs[off] = v;
            s[ch] += v;
            q[ch] += v * v;
        }
    }
    __syncthreads();

    float mu[4], rs[4];
    #pragma unroll
    for (int ch = 0; ch < 4; ch++) {
        float smv = blockReduceSum(s[ch], red);
        float sq  = blockReduceSum(q[ch], red);
        mu[ch] = smv * invH;
        float var = sq * invH - mu[ch] * mu[ch];
        rs[ch] = rsqrtf(var + 1e-5f);
    }

    float nc_r[3], so_r[3];
    float sc_acc = 0.0f, qc_acc = 0.0f;
    #pragma unroll
    for (int it = 0; it < 3; it++) {
        int u = threadIdx.x + it * 256;
        if (u < H) {
            float iv = (zs[0 * H + u] - mu[0]) * rs[0] * gg[0 * H + u] + bg[0 * H + u];
            float jv = (zs[1 * H + u] - mu[1]) * rs[1] * gg[1 * H + u] + bg[1 * H + u];
            float fv = (zs[2 * H + u] - mu[2]) * rs[2] * gg[2 * H + u] + bg[2 * H + u];
            float ov = (zs[3 * H + u] - mu[3]) * rs[3] * gg[3 * H + u] + bg[3 * H + u];
            float cold = c[(size_t)b * H + u];
            float nc = cold * sigm(fv + 1.0f) + sigm(iv) * tanhf(jv);
            nc_r[it] = nc;
            so_r[it] = sigm(ov);
            sc_acc += nc;
            qc_acc += nc * nc;
        }
    }
    float smc = blockReduceSum(sc_acc, red);
    float sqc = blockReduceSum(qc_acc, red);
    float muc = smc * invH;
    float rsc = rsqrtf(sqc * invH - muc * muc + 1e-5f);

    #pragma unroll
    for (int it = 0; it < 3; it++) {
        int u = threadIdx.x + it * 256;
        if (u < H) {
            float nc = nc_r[it];
            float nh = tanhf((nc - muc) * rsc * gc[u] + bc[u]) * so_r[it];
            float hold = h[(size_t)b * H + u];
            float cold = c[(size_t)b * H + u];
            float hn = 0.9f * nh + 0.1f * hold;
            float cn = 0.5f * nc + 0.5f * cold;
            h[(size_t)b * H + u] = hn;
            c[(size_t)b * H + u] = cn;
            bf16 sh_, sm_, sl_;
            split3(hn, sh_, sm_, sl_);
            size_t so = (size_t)b * sp_lda + u;
            sph[so] = sh_; spm[so] = sm_; spl[so] = sl_;
            if (hih) {
                size_t ho = ((size_t)b * T_ + t) * HI_LDA + u;
                hih[ho] = sh_; him[ho] = sm_; hil[ho] = sl_;
            }
        }
    }
}

// ---------------------------------------------------------------------------
// Init + tail copy
// ---------------------------------------------------------------------------
__global__ void init_states()
{
    int i = blockIdx.x * blockDim.x + threadIdx.x;
    int stride = gridDim.x * blockDim.x;
    const bf16 bz = __float2bfloat16(0.0f);
    for (int j = i; j < B_ * F_; j += stride) { g_fh[j] = 0.0f; g_fc[j] = 0.0f; }
    for (int j = i; j < B_ * S_; j += stride) { g_sh[j] = 0.0f; g_sc[j] = 0.0f; }
    for (int j = i; j < B_ * FH_LDA; j += stride) { g_fhh[j] = bz; g_fhm[j] = bz; g_fhl[j] = bz; }
    for (int j = i; j < B_ * SH_LDA; j += stride) { g_shh[j] = bz; g_shm[j] = bz; g_shl[j] = bz; }
    for (int j = i; j < B_ * T_ * 4; j += stride) {
        size_t off = (size_t)(j >> 2) * HI_LDA + F_ + (j & 3);
        g_hih[off] = bz; g_him[off] = bz; g_hil[off] = bz;
    }
}

__global__ void tail_copy(float* __restrict__ out, size_t out_total)
{
    int i = blockIdx.x * blockDim.x + threadIdx.x;
    const size_t base = (size_t)B_ * T_ * V_;
    const int nF = B_ * F_, nS = B_ * S_;
    const int total = 2 * nF + 2 * nS;
    if (i >= total) return;
    float v;
    size_t off = base + i;
    if (i < nF)               v = g_fh[i];
    else if (i < 2 * nF)      v = g_fc[i - nF];
    else if (i < 2 * nF + nS) v = g_sh[i - 2 * nF];
    else                      v = g_sc[i - 2 * nF - nS];
    if (off < out_total) out[off] = v;
}

// ---------------------------------------------------------------------------
// Launch
// ---------------------------------------------------------------------------
extern "C" void kernel_launch(void* const* d_in, const int* in_sizes, int n_in,
                              void* d_out, int out_size)
{
    const float* inputs = (const float*)d_in[0];
    const float* W0  = (const float*)d_in[1];
    const float* b0  = (const float*)d_in[2];
    const float* g0  = (const float*)d_in[3];
    const float* bg0 = (const float*)d_in[4];
    const float* gc0 = (const float*)d_in[5];
    const float* bc0 = (const float*)d_in[6];
    const float* W1  = (const float*)d_in[7];
    const float* b1  = (const float*)d_in[8];
    const float* g1  = (const float*)d_in[9];
    const float* bg1 = (const float*)d_in[10];
    const float* gc1 = (const float*)d_in[11];
    const float* bc1 = (const float*)d_in[12];
    const float* WS  = (const float*)d_in[13];
    const float* bS  = (const float*)d_in[14];
    const float* gS  = (const float*)d_in[15];
    const float* bgS = (const float*)d_in[16];
    const float* gcS = (const float*)d_in[17];
    const float* bcS = (const float*)d_in[18];
    const float* Wout = (const float*)d_in[19];
    const float* bout = (const float*)d_in[20];
    float* out = (float*)d_out;

    float *fh, *fc, *sh, *sc, *z, *zS;
    bf16 *xh, *xm, *xl, *fhh, *fhm, *fhl, *shh, *shm, *shl, *hih, *him, *hil;
    bf16 *W0h, *W0m, *W0l, *WSh, *WSm, *WSl, *W1h, *W1m, *W1l, *Woh, *Wom, *Wol;
    cudaGetSymbolAddress((void**)&fh,  g_fh);  cudaGetSymbolAddress((void**)&fc,  g_fc);
    cudaGetSymbolAddress((void**)&sh,  g_sh);  cudaGetSymbolAddress((void**)&sc,  g_sc);
    cudaGetSymbolAddress((void**)&z,   g_z);   cudaGetSymbolAddress((void**)&zS,  g_zS);
    cudaGetSymbolAddress((void**)&xh,  g_xh);  cudaGetSymbolAddress((void**)&xm,  g_xm);  cudaGetSymbolAddress((void**)&xl,  g_xl);
    cudaGetSymbolAddress((void**)&fhh, g_fhh); cudaGetSymbolAddress((void**)&fhm, g_fhm); cudaGetSymbolAddress((void**)&fhl, g_fhl);
    cudaGetSymbolAddress((void**)&shh, g_shh); cudaGetSymbolAddress((void**)&shm, g_shm); cudaGetSymbolAddress((void**)&shl, g_shl);
    cudaGetSymbolAddress((void**)&hih, g_hih); cudaGetSymbolAddress((void**)&him, g_him); cudaGetSymbolAddress((void**)&hil, g_hil);
    cudaGetSymbolAddress((void**)&W0h, g_W0h); cudaGetSymbolAddress((void**)&W0m, g_W0m); cudaGetSymbolAddress((void**)&W0l, g_W0l);
    cudaGetSymbolAddress((void**)&WSh, g_WSh); cudaGetSymbolAddress((void**)&WSm, g_WSm); cudaGetSymbolAddress((void**)&WSl, g_WSl);
    cudaGetSymbolAddress((void**)&W1h, g_W1h); cudaGetSymbolAddress((void**)&W1m, g_W1m); cudaGetSymbolAddress((void**)&W1l, g_W1l);
    cudaGetSymbolAddress((void**)&Woh, g_Woh); cudaGetSymbolAddress((void**)&Wom, g_Wom); cudaGetSymbolAddress((void**)&Wol, g_Wol);

    const int SM64  = 3 * 2 * ASZ + 3 * 2 * (64 * ARP);    // 92160
    const int SM128 = 2 * 2 * ASZ + 2 * 2 * (128 * ARP);   // 81920
    cudaFuncSetAttribute(gemm_split<64, 1>,  cudaFuncAttributeMaxDynamicSharedMemorySize, SM64);
    cudaFuncSetAttribute(gemm_split<128, 2>, cudaFuncAttributeMaxDynamicSharedMemorySize, SM128);

    // Weight transpose + split
    {
        long n;
        n = (long)4 * F_ * 832;
        transpose_split<<<(unsigned)((n + 255) / 256), 256>>>(W0, W0h, W0m, W0l, 4 * F_, 832, 828, 0, 828);
        n = (long)4 * S_ * 1120;
        transpose_split<<<(unsigned)((n + 255) / 256), 256>>>(WS, WSh, WSm, WSl, 4 * S_, 1120, 700, 4, 1100);
        n = (long)4 * F_ * 1120;
        transpose_split<<<(unsigned)((n + 255) / 256), 256>>>(W1, W1h, W1m, W1l, 4 * F_, 1120, 1100, 0, 1100);
        n = (long)V_ * 704;
        transpose_split<<<(unsigned)((n + 255) / 256), 256>>>(Wout, Woh, Wom, Wol, V_, 704, 700, 0, 700);
    }
    {
        long n = (long)B_ * T_ * E_;
        split_inputs<<<(unsigned)((n + 255) / 256), 256>>>(inputs);
    }
    init_states<<<148, 256>>>();

    const size_t psC = (size_t)B_ * 4 * F_;
    const size_t psS = (size_t)B_ * 4 * S_;
    const dim3 gC((4 * F_ + 63) / 64, 1, KS_CELL);   // 44 x 3 = 132 CTAs
    const dim3 gSl((4 * S_ + 63) / 64, 1, KS_SLOW);  // 25 x 5 = 125 CTAs

    for (int t = 0; t < T_; t++) {
        // Fast cell 0: A = [x_t | fh], Kpad=832, K1p=128
        gemm_split<64, 1><<<gC, 256, SM64>>>(
            xh + (size_t)t * E_, xm + (size_t)t * E_, xl + (size_t)t * E_, (long)T_ * E_, 128,
            fhh, fhm, fhl, FH_LDA,
            W0h, W0m, W0l, 832, nullptr, z, 4 * F_, psC, 4 * F_, 832);
        lstm_pw<<<B_, 256>>>(z, psC, KS_CELL, b0, fh, fc, F_, g0, bg0, gc0, bc0,
                             fhh, fhm, fhl, FH_LDA, nullptr, nullptr, nullptr, 0);

        // Slow cell: A = [fh | gap4 | sh], Kpad=1120, K1p=704
        gemm_split<64, 1><<<gSl, 256, SM64>>>(
            fhh, fhm, fhl, FH_LDA, 704,
            shh, shm, shl, SH_LDA,
            WSh, WSm, WSl, 1120, nullptr, zS, 4 * S_, psS, 4 * S_, 1120);
        lstm_pw<<<B_, 256>>>(zS, psS, KS_SLOW, bS, sh, sc, S_, gS, bgS, gcS, bcS,
                             shh, shm, shl, SH_LDA, nullptr, nullptr, nullptr, 0);

        // Fast cell 1: A = [sh | fh], Kpad=1120, K1p=400
        gemm_split<64, 1><<<gC, 256, SM64>>>(
            shh, shm, shl, SH_LDA, 400,
            fhh, fhm, fhl, FH_LDA,
            W1h, W1m, W1l, 1120, nullptr, z, 4 * F_, psC, 4 * F_, 1120);
        lstm_pw<<<B_, 256>>>(z, psC, KS_CELL, b1, fh, fc, F_, g1, bg1, gc1, bc1,
                             fhh, fhm, fhl, FH_LDA, hih, him, hil, t);
    }

    // Output projection (x3, h/m splits only): hist[12800,704] @ Wout^T + bias
    {
        const dim3 grid((V_ + 127) / 128, (B_ * T_) / 128, 1);   // 79 x 100
        gemm_split<128, 2><<<grid, 256, SM128>>>(
            hih, him, hil, HI_LDA, 704,
            hih, him, hil, HI_LDA,
            Woh, Wom, Wol, 704, bout, out, V_, 0, V_, 704);
    }

    {
        int total = 2 * B_ * F_ + 2 * B_ * S_;
        tail_copy<<<(total + 255) / 256, 256>>>(out, (size_t)out_size);
    }
}

// round 10
// speedup vs baseline: 4.8663x; 1.1473x over previous
#include <cuda_runtime.h>
#include <cuda_bf16.h>
#include <cstdint>

// Problem constants
#define B_  128
#define T_  100
#define E_  128
#define F_  700
#define S_  400
#define V_  10000

#define FH_LDA 720
#define SH_LDA 424
#define HI_LDA 704

#define KS_CELL 3
#define KS_SLOW 5
#define GRID_P  132          // persistent grid (44*3)

typedef __nv_bfloat16 bf16;

// ---------------------------------------------------------------------------
// Static device scratch
// ---------------------------------------------------------------------------
__device__ float g_fh[B_ * F_];
__device__ float g_fc[B_ * F_];
__device__ float g_sh[B_ * S_];
__device__ float g_sc[B_ * S_];
__device__ float g_z [KS_CELL * B_ * 4 * F_];
__device__ float g_zS[KS_SLOW * B_ * 4 * S_];

__device__ bf16 g_xh[B_ * T_ * E_], g_xm[B_ * T_ * E_], g_xl[B_ * T_ * E_];
__device__ bf16 g_fhh[B_ * FH_LDA], g_fhm[B_ * FH_LDA], g_fhl[B_ * FH_LDA];
__device__ bf16 g_shh[B_ * SH_LDA], g_shm[B_ * SH_LDA], g_shl[B_ * SH_LDA];
__device__ bf16 g_hih[(size_t)B_ * T_ * HI_LDA], g_him[(size_t)B_ * T_ * HI_LDA], g_hil[(size_t)B_ * T_ * HI_LDA];

__device__ bf16 g_W0h[(size_t)4 * F_ * 832],  g_W0m[(size_t)4 * F_ * 832],  g_W0l[(size_t)4 * F_ * 832];
__device__ bf16 g_WSh[(size_t)4 * S_ * 1120], g_WSm[(size_t)4 * S_ * 1120], g_WSl[(size_t)4 * S_ * 1120];
__device__ bf16 g_W1h[(size_t)4 * F_ * 1120], g_W1m[(size_t)4 * F_ * 1120], g_W1l[(size_t)4 * F_ * 1120];
__device__ bf16 g_Woh[(size_t)V_ * 704],      g_Wom[(size_t)V_ * 704],      g_Wol[(size_t)V_ * 704];

// Grid barrier state
__device__ unsigned g_barcnt;
__device__ unsigned g_bargen;

// ---------------------------------------------------------------------------
// Helpers
// ---------------------------------------------------------------------------
__device__ __forceinline__ uint32_t smem_u32(const void* p) {
    uint32_t a;
    asm("{ .reg .u64 t; cvta.to.shared.u64 t, %1; cvt.u32.u64 %0, t; }" : "=r"(a) : "l"(p));
    return a;
}
__device__ __forceinline__ void split3(float x, bf16& h, bf16& m, bf16& l) {
    h = __float2bfloat16(x);
    float r = x - __bfloat162float(h);
    m = __float2bfloat16(r);
    float r2 = r - __bfloat162float(m);
    l = __float2bfloat16(r2);
}
__device__ __forceinline__ void mma_bf16(float c[4], const uint32_t a[4], const uint32_t b[2]) {
    asm volatile("mma.sync.aligned.m16n8k16.row.col.f32.bf16.bf16.f32 "
                 "{%0,%1,%2,%3}, {%4,%5,%6,%7}, {%8,%9}, {%0,%1,%2,%3};"
                 : "+f"(c[0]), "+f"(c[1]), "+f"(c[2]), "+f"(c[3])
                 : "r"(a[0]), "r"(a[1]), "r"(a[2]), "r"(a[3]), "r"(b[0]), "r"(b[1]));
}
#define CP16(dst, src, sz) \
    asm volatile("cp.async.cg.shared.global [%0], [%1], 16, %2;" \
                 :: "r"(dst), "l"(src), "r"(sz))
#define CP_COMMIT() asm volatile("cp.async.commit_group;" ::: "memory")
#define CP_WAIT1()  asm volatile("cp.async.wait_group 1;" ::: "memory")
#define CP_WAIT0()  asm volatile("cp.async.wait_group 0;" ::: "memory")

#define ARP   80
#define ASZ   (128 * ARP)            // 10240 bytes per A split-buffer

// ---------------------------------------------------------------------------
// Software grid barrier (all GRID_P CTAs co-resident; release/acquire).
// ---------------------------------------------------------------------------
__device__ __forceinline__ void gbar(unsigned& mygen) {
    __syncthreads();
    __threadfence();
    if (threadIdx.x == 0) {
        unsigned prev = atomicAdd(&g_barcnt, 1u);
        if (prev == (unsigned)(gridDim.x - 1)) {
            atomicExch(&g_barcnt, 0u);
            __threadfence();
            atomicAdd(&g_bargen, 1u);
        } else {
            volatile unsigned* vg = &g_bargen;
            while (*vg <= mygen) __nanosleep(128);
        }
    }
    mygen++;
    __syncthreads();
    __threadfence();
}

// ---------------------------------------------------------------------------
// GEMM phase (device fn), BN=64, 3 bf16 splits, 6 products, H*H unchained.
// Writes split-K partials (no bias). M = 128 fixed.
// ---------------------------------------------------------------------------
__device__ void gemm_phase(char* sm,
    const bf16* __restrict__ A1h, const bf16* __restrict__ A1m, const bf16* __restrict__ A1l,
    int lda1, int K1p,
    const bf16* __restrict__ A2h, const bf16* __restrict__ A2m, const bf16* __restrict__ A2l,
    int lda2,
    const bf16* __restrict__ Wh, const bf16* __restrict__ Wm, const bf16* __restrict__ Wl,
    int ldw,
    float* __restrict__ C, int ldc, int pstride,
    int Kpad, int N, int tnc, int KS)
{
    constexpr int NT  = 4;
    constexpr int BSZ = 64 * ARP;             // 5120
    constexpr uint32_t BBASE = 6 * ASZ;       // 61440

    const int cta = blockIdx.x;
    if (cta >= tnc * KS) return;

    const uint32_t sbase = smem_u32(sm);
    const int tid  = threadIdx.x;
    const int wid  = tid >> 5;
    const int lane = tid & 31;
    const int wm   = wid & 3;
    const int wn   = wid >> 2;
    const int n0   = (cta % tnc) * 64;
    const int kz   = cta / tnc;
    const int nk   = Kpad >> 5;
    const int nkq  = (nk + KS - 1) / KS;
    const int i0   = kz * nkq;
    const int i1   = (i0 + nkq < nk) ? (i0 + nkq) : nk;

    const bf16* A1s[3] = {A1h, A1m, A1l};
    const bf16* A2s[3] = {A2h, A2m, A2l};
    const bf16* Ws [3] = {Wh,  Wm,  Wl};

    float acc[2][NT][4], accs[2][NT][4];
    #pragma unroll
    for (int mt = 0; mt < 2; mt++)
        #pragma unroll
        for (int nt = 0; nt < NT; nt++)
            #pragma unroll
            for (int r = 0; r < 4; r++) { acc[mt][nt][r] = 0.0f; accs[mt][nt][r] = 0.0f; }

    auto load_chunk = [&](int i) {
        const int k0 = i << 5;
        const int buf = i & 1;
        #pragma unroll
        for (int it = 0; it < 6; it++) {
            const int sp  = it >> 1;
            const int idx = ((it & 1) << 8) + tid;
            const int r   = idx >> 2;
            const int c4  = idx & 3;
            const int gk  = k0 + (c4 << 3);
            const bf16* src = (gk < K1p) ? A1s[sp] + r * lda1 + gk
                                         : A2s[sp] + r * lda2 + (gk - K1p);
            CP16(sbase + sp * (2 * ASZ) + buf * ASZ + r * ARP + c4 * 16, src, 16);
        }
        #pragma unroll
        for (int it = 0; it < 3; it++) {
            const int sp  = it;
            const int r   = tid >> 2;
            const int c4  = tid & 3;
            const int n   = n0 + r;
            const int nc  = (n < N) ? n : (N - 1);
            const bf16* src = Ws[sp] + (long)nc * ldw + k0 + (c4 << 3);
            CP16(sbase + BBASE + sp * (2 * BSZ) + buf * BSZ + r * ARP + c4 * 16,
                 src, (n < N) ? 16 : 0);
        }
        CP_COMMIT();
    };

    if (i0 < i1) load_chunk(i0);
    for (int i = i0; i < i1; i++) {
        if (i + 1 < i1) { load_chunk(i + 1); CP_WAIT1(); }
        else            { CP_WAIT0(); }
        __syncthreads();
        const int buf = i & 1;

        #pragma unroll
        for (int ks = 0; ks < 2; ks++) {
            const uint32_t kb = (ks << 5) + ((lane & 3) << 2);
            uint32_t a[3][2][4];
            #pragma unroll
            for (int sp = 0; sp < 3; sp++)
                #pragma unroll
                for (int mt = 0; mt < 2; mt++) {
                    const char* base = sm + sp * (2 * ASZ) + buf * ASZ
                                     + (wm * 32 + mt * 16 + (lane >> 2)) * ARP + kb;
                    a[sp][mt][0] = *(const uint32_t*)(base);
                    a[sp][mt][1] = *(const uint32_t*)(base + 8 * ARP);
                    a[sp][mt][2] = *(const uint32_t*)(base + 16);
                    a[sp][mt][3] = *(const uint32_t*)(base + 8 * ARP + 16);
                }
            uint32_t b[3][NT][2];
            #pragma unroll
            for (int sp = 0; sp < 3; sp++)
                #pragma unroll
                for (int nt = 0; nt < NT; nt++) {
                    const char* base = sm + BBASE + sp * (2 * BSZ) + buf * BSZ
                                     + (wn * 32 + nt * 8 + (lane >> 2)) * ARP + kb;
                    b[sp][nt][0] = *(const uint32_t*)(base);
                    b[sp][nt][1] = *(const uint32_t*)(base + 16);
                }
            #pragma unroll
            for (int mt = 0; mt < 2; mt++)
                #pragma unroll
                for (int nt = 0; nt < NT; nt++) {
                    mma_bf16(accs[mt][nt], a[0][mt], b[2][nt]);  // H*L
                    mma_bf16(accs[mt][nt], a[1][mt], b[1][nt]);  // M*M
                    mma_bf16(accs[mt][nt], a[2][mt], b[0][nt]);  // L*H
                    mma_bf16(accs[mt][nt], a[0][mt], b[1][nt]);  // H*M
                    mma_bf16(accs[mt][nt], a[1][mt], b[0][nt]);  // M*H
                    float d[4] = {0.f, 0.f, 0.f, 0.f};           // H*H unchained
                    mma_bf16(d, a[0][mt], b[0][nt]);
                    acc[mt][nt][0] += d[0];
                    acc[mt][nt][1] += d[1];
                    acc[mt][nt][2] += d[2];
                    acc[mt][nt][3] += d[3];
                }
        }
        __syncthreads();
    }

    float* Cp = C + (size_t)kz * pstride;
    #pragma unroll
    for (int mt = 0; mt < 2; mt++) {
        int gm = wm * 32 + mt * 16 + (lane >> 2);
        #pragma unroll
        for (int nt = 0; nt < NT; nt++) {
            int gn = n0 + wn * 32 + nt * 8 + ((lane & 3) << 1);
            if (gn < N) {
                float r0 = acc[mt][nt][0] + accs[mt][nt][0];
                float r1 = acc[mt][nt][1] + accs[mt][nt][1];
                float r2 = acc[mt][nt][2] + accs[mt][nt][2];
                float r3 = acc[mt][nt][3] + accs[mt][nt][3];
                *(float2*)(Cp + (size_t)gm * ldc + gn)       = make_float2(r0, r1);
                *(float2*)(Cp + (size_t)(gm + 8) * ldc + gn) = make_float2(r2, r3);
            }
        }
    }
}

// ---------------------------------------------------------------------------
// Pointwise phase (device fn). z partials read with __ldcg (L1 bypass —
// written by other SMs; persistent kernel keeps L1 across steps).
// ---------------------------------------------------------------------------
__device__ __forceinline__ float sigm(float x) { return 1.0f / (1.0f + __expf(-x)); }

__device__ __forceinline__ float blockReduceSum(float v, float* red) {
    int lane = threadIdx.x & 31;
    int w    = threadIdx.x >> 5;
    #pragma unroll
    for (int o = 16; o > 0; o >>= 1) v += __shfl_down_sync(0xffffffffu, v, o);
    if (lane == 0) red[w] = v;
    __syncthreads();
    float r = 0.0f;
    if (w == 0) {
        int nw = blockDim.x >> 5;
        r = (lane < nw) ? red[lane] : 0.0f;
        #pragma unroll
        for (int o = 16; o > 0; o >>= 1) r += __shfl_down_sync(0xffffffffu, r, o);
        if (lane == 0) red[0] = r;
    }
    __syncthreads();
    r = red[0];
    __syncthreads();
    return r;
}

__device__ void pw_phase(char* smraw,
    const float* __restrict__ zp, int pstride, int nparts,
    const float* __restrict__ bias,
    float* __restrict__ h, float* __restrict__ c, int H,
    const float* __restrict__ gg, const float* __restrict__ bg,
    const float* __restrict__ gc, const float* __restrict__ bc,
    bf16* __restrict__ sph, bf16* __restrict__ spm, bf16* __restrict__ spl, int sp_lda,
    bf16* __restrict__ hih, bf16* __restrict__ him, bf16* __restrict__ hil, int t)
{
    const int b = blockIdx.x;
    if (b >= B_) return;
    float* zs  = (float*)smraw;          // 4*H floats
    float* red = zs + 4 * F_;            // 32 floats
    const float invH = 1.0f / (float)H;
    const size_t rowoff = (size_t)b * 4 * H;

    float s[4] = {0, 0, 0, 0}, q[4] = {0, 0, 0, 0};
    for (int u = threadIdx.x; u < H; u += blockDim.x) {
        #pragma unroll
        for (int ch = 0; ch < 4; ch++) {
            const int off = ch * H + u;
            float v = bias[off];
            for (int p = 0; p < nparts; p++)
                v += __ldcg(zp + (size_t)p * pstride + rowoff + off);
            zs[off] = v;
            s[ch] += v;
            q[ch] += v * v;
        }
    }
    __syncthreads();

    float mu[4], rs[4];
    #pragma unroll
    for (int ch = 0; ch < 4; ch++) {
        float smv = blockReduceSum(s[ch], red);
        float sq  = blockReduceSum(q[ch], red);
        mu[ch] = smv * invH;
        float var = sq * invH - mu[ch] * mu[ch];
        rs[ch] = rsqrtf(var + 1e-5f);
    }

    float nc_r[3], so_r[3];
    float sc_acc = 0.0f, qc_acc = 0.0f;
    #pragma unroll
    for (int it = 0; it < 3; it++) {
        int u = threadIdx.x + it * 256;
        if (u < H) {
            float iv = (zs[0 * H + u] - mu[0]) * rs[0] * gg[0 * H + u] + bg[0 * H + u];
            float jv = (zs[1 * H + u] - mu[1]) * rs[1] * gg[1 * H + u] + bg[1 * H + u];
            float fv = (zs[2 * H + u] - mu[2]) * rs[2] * gg[2 * H + u] + bg[2 * H + u];
            float ov = (zs[3 * H + u] - mu[3]) * rs[3] * gg[3 * H + u] + bg[3 * H + u];
            float cold = c[(size_t)b * H + u];
            float nc = cold * sigm(fv + 1.0f) + sigm(iv) * tanhf(jv);
            nc_r[it] = nc;
            so_r[it] = sigm(ov);
            sc_acc += nc;
            qc_acc += nc * nc;
        }
    }
    float smc = blockReduceSum(sc_acc, red);
    float sqc = blockReduceSum(qc_acc, red);
    float muc = smc * invH;
    float rsc = rsqrtf(sqc * invH - muc * muc + 1e-5f);

    #pragma unroll
    for (int it = 0; it < 3; it++) {
        int u = threadIdx.x + it * 256;
        if (u < H) {
            float nc = nc_r[it];
            float nh = tanhf((nc - muc) * rsc * gc[u] + bc[u]) * so_r[it];
            float hold = h[(size_t)b * H + u];
            float cold = c[(size_t)b * H + u];
            float hn = 0.9f * nh + 0.1f * hold;
            float cn = 0.5f * nc + 0.5f * cold;
            h[(size_t)b * H + u] = hn;
            c[(size_t)b * H + u] = cn;
            bf16 sh_, sm_, sl_;
            split3(hn, sh_, sm_, sl_);
            size_t so = (size_t)b * sp_lda + u;
            sph[so] = sh_; spm[so] = sm_; spl[so] = sl_;
            if (hih) {
                size_t ho = ((size_t)b * T_ + t) * HI_LDA + u;
                hih[ho] = sh_; him[ho] = sm_; hil[ho] = sl_;
            }
        }
    }
}

// ---------------------------------------------------------------------------
// Persistent recurrence kernel: 100 steps x 6 phases, software grid barriers.
// ---------------------------------------------------------------------------
struct RecParams {
    const bf16 *xh, *xm, *xl;
    const float *b0, *g0, *bg0, *gc0, *bc0;
    const float *bS, *gS, *bgS, *gcS, *bcS;
    const float *b1, *g1, *bg1, *gc1, *bc1;
    const bf16 *W0h, *W0m, *W0l, *WSh, *WSm, *WSl, *W1h, *W1m, *W1l;
    float *fh, *fc, *sh, *sc, *z, *zS;
    bf16 *fhh, *fhm, *fhl, *shh, *shm, *shl, *hih, *him, *hil;
};

__global__ void __launch_bounds__(256)
rec_persist(RecParams P)
{
    extern __shared__ char sm[];
    unsigned mygen = 0;
    const int psC = B_ * 4 * F_;
    const int psS = B_ * 4 * S_;

    for (int t = 0; t < T_; t++) {
        // Fast cell 0: A = [x_t | fh], Kpad=832, K1p=128
        gemm_phase(sm, P.xh + t * E_, P.xm + t * E_, P.xl + t * E_, T_ * E_, 128,
                   P.fhh, P.fhm, P.fhl, FH_LDA,
                   P.W0h, P.W0m, P.W0l, 832,
                   P.z, 4 * F_, psC, 832, 4 * F_, 44, KS_CELL);
        gbar(mygen);
        pw_phase(sm, P.z, psC, KS_CELL, P.b0, P.fh, P.fc, F_,
                 P.g0, P.bg0, P.gc0, P.bc0,
                 P.fhh, P.fhm, P.fhl, FH_LDA, nullptr, nullptr, nullptr, 0);
        gbar(mygen);

        // Slow cell: A = [fh | gap4 | sh], Kpad=1120, K1p=704
        gemm_phase(sm, P.fhh, P.fhm, P.fhl, FH_LDA, 704,
                   P.shh, P.shm, P.shl, SH_LDA,
                   P.WSh, P.WSm, P.WSl, 1120,
                   P.zS, 4 * S_, psS, 1120, 4 * S_, 25, KS_SLOW);
        gbar(mygen);
        pw_phase(sm, P.zS, psS, KS_SLOW, P.bS, P.sh, P.sc, S_,
                 P.gS, P.bgS, P.gcS, P.bcS,
                 P.shh, P.shm, P.shl, SH_LDA, nullptr, nullptr, nullptr, 0);
        gbar(mygen);

        // Fast cell 1: A = [sh | fh], Kpad=1120, K1p=400
        gemm_phase(sm, P.shh, P.shm, P.shl, SH_LDA, 400,
                   P.fhh, P.fhm, P.fhl, FH_LDA,
                   P.W1h, P.W1m, P.W1l, 1120,
                   P.z, 4 * F_, psC, 1120, 4 * F_, 44, KS_CELL);
        gbar(mygen);
        pw_phase(sm, P.z, psC, KS_CELL, P.b1, P.fh, P.fc, F_,
                 P.g1, P.bg1, P.gc1, P.bc1,
                 P.fhh, P.fhm, P.fhl, FH_LDA, P.hih, P.him, P.hil, t);
        gbar(mygen);
    }
}

// ---------------------------------------------------------------------------
// Projection GEMM kernel (x3: HH + HM + MH, bias) — BN=128, standalone.
// ---------------------------------------------------------------------------
__global__ void __launch_bounds__(256)
gemm_proj(const bf16* __restrict__ Ah, const bf16* __restrict__ Am, long lda,
          const bf16* __restrict__ Wh, const bf16* __restrict__ Wm, int ldw,
          const float* __restrict__ bias,
          float* __restrict__ C, long ldc, int N, int Kpad)
{
    constexpr int NT  = 8;
    constexpr int BSZ = 128 * ARP;            // 10240
    constexpr uint32_t BBASE = 4 * ASZ;       // 40960

    extern __shared__ char sm[];
    const uint32_t sbase = smem_u32(sm);
    const int tid  = threadIdx.x;
    const int wid  = tid >> 5;
    const int lane = tid & 31;
    const int wm   = wid & 3;
    const int wn   = wid >> 2;
    const int n0   = blockIdx.x * 128;
    const long m0  = (long)blockIdx.y * 128;
    const int nk   = Kpad >> 5;

    const bf16* As[2] = {Ah, Am};
    const bf16* Ws[2] = {Wh, Wm};

    float acc[2][NT][4];
    #pragma unroll
    for (int mt = 0; mt < 2; mt++)
        #pragma unroll
        for (int nt = 0; nt < NT; nt++)
            #pragma unroll
            for (int r = 0; r < 4; r++) acc[mt][nt][r] = 0.0f;

    auto load_chunk = [&](int i) {
        const int k0 = i << 5;
        const int buf = i & 1;
        #pragma unroll
        for (int it = 0; it < 4; it++) {
            const int sp  = it >> 1;
            const int idx = ((it & 1) << 8) + tid;
            const int r   = idx >> 2;
            const int c4  = idx & 3;
            CP16(sbase + sp * (2 * ASZ) + buf * ASZ + r * ARP + c4 * 16,
                 As[sp] + (m0 + r) * lda + k0 + (c4 << 3), 16);
        }
        #pragma unroll
        for (int it = 0; it < 4; it++) {
            const int sp  = it >> 1;
            const int idx = ((it & 1) << 8) + tid;
            const int r   = idx >> 2;
            const int c4  = idx & 3;
            const int n   = n0 + r;
            const int nc  = (n < N) ? n : (N - 1);
            CP16(sbase + BBASE + sp * (2 * BSZ) + buf * BSZ + r * ARP + c4 * 16,
                 Ws[sp] + (long)nc * ldw + k0 + (c4 << 3), (n < N) ? 16 : 0);
        }
        CP_COMMIT();
    };

    load_chunk(0);
    for (int i = 0; i < nk; i++) {
        if (i + 1 < nk) { load_chunk(i + 1); CP_WAIT1(); }
        else            { CP_WAIT0(); }
        __syncthreads();
        const int buf = i & 1;

        #pragma unroll
        for (int ks = 0; ks < 2; ks++) {
            const uint32_t kb = (ks << 5) + ((lane & 3) << 2);
            uint32_t a[2][2][4];
            #pragma unroll
            for (int sp = 0; sp < 2; sp++)
                #pragma unroll
                for (int mt = 0; mt < 2; mt++) {
                    const char* base = sm + sp * (2 * ASZ) + buf * ASZ
                                     + (wm * 32 + mt * 16 + (lane >> 2)) * ARP + kb;
                    a[sp][mt][0] = *(const uint32_t*)(base);
                    a[sp][mt][1] = *(const uint32_t*)(base + 8 * ARP);
                    a[sp][mt][2] = *(const uint32_t*)(base + 16);
                    a[sp][mt][3] = *(const uint32_t*)(base + 8 * ARP + 16);
                }
            uint32_t b[2][NT][2];
            #pragma unroll
            for (int sp = 0; sp < 2; sp++)
                #pragma unroll
                for (int nt = 0; nt < NT; nt++) {
                    const char* base = sm + BBASE + sp * (2 * BSZ) + buf * BSZ
                                     + (wn * 64 + nt * 8 + (lane >> 2)) * ARP + kb;
                    b[sp][nt][0] = *(const uint32_t*)(base);
                    b[sp][nt][1] = *(const uint32_t*)(base + 16);
                }
            #pragma unroll
            for (int mt = 0; mt < 2; mt++)
                #pragma unroll
                for (int nt = 0; nt < NT; nt++) {
                    mma_bf16(acc[mt][nt], a[0][mt], b[1][nt]);  // H*M
                    mma_bf16(acc[mt][nt], a[1][mt], b[0][nt]);  // M*H
                    mma_bf16(acc[mt][nt], a[0][mt], b[0][nt]);  // H*H
                }
        }
        __syncthreads();
    }

    #pragma unroll
    for (int mt = 0; mt < 2; mt++) {
        long gm = m0 + wm * 32 + mt * 16 + (lane >> 2);
        #pragma unroll
        for (int nt = 0; nt < NT; nt++) {
            int gn = n0 + wn * 64 + nt * 8 + ((lane & 3) << 1);
            if (gn < N) {
                float2 bv = *(const float2*)(bias + gn);
                *(float2*)(C + gm * ldc + gn) =
                    make_float2(acc[mt][nt][0] + bv.x, acc[mt][nt][1] + bv.y);
                *(float2*)(C + (gm + 8) * ldc + gn) =
                    make_float2(acc[mt][nt][2] + bv.x, acc[mt][nt][3] + bv.y);
            }
        }
    }
}

// ---------------------------------------------------------------------------
// Setup kernels
// ---------------------------------------------------------------------------
__global__ void transpose_split(const float* __restrict__ in,
                                bf16* __restrict__ oh, bf16* __restrict__ om, bf16* __restrict__ ol,
                                int N, int ldw, int K1, int gap, int Ktot)
{
    long idx = (long)blockIdx.x * blockDim.x + threadIdx.x;
    long total = (long)N * ldw;
    if (idx >= total) return;
    int n = (int)(idx / ldw);
    int k = (int)(idx % ldw);
    float v = 0.0f;
    if (k < K1)                               v = in[(long)k * N + n];
    else if (k >= K1 + gap && k < Ktot + gap) v = in[(long)(k - gap) * N + n];
    bf16 h, m, l;
    split3(v, h, m, l);
    oh[idx] = h; om[idx] = m; ol[idx] = l;
}

__global__ void split_inputs(const float* __restrict__ in)
{
    long idx = (long)blockIdx.x * blockDim.x + threadIdx.x;
    if (idx >= (long)B_ * T_ * E_) return;
    bf16 h, m, l;
    split3(in[idx], h, m, l);
    g_xh[idx] = h; g_xm[idx] = m; g_xl[idx] = l;
}

__global__ void init_states()
{
    int i = blockIdx.x * blockDim.x + threadIdx.x;
    int stride = gridDim.x * blockDim.x;
    const bf16 bz = __float2bfloat16(0.0f);
    if (i == 0) { g_barcnt = 0u; g_bargen = 0u; }
    for (int j = i; j < B_ * F_; j += stride) { g_fh[j] = 0.0f; g_fc[j] = 0.0f; }
    for (int j = i; j < B_ * S_; j += stride) { g_sh[j] = 0.0f; g_sc[j] = 0.0f; }
    for (int j = i; j < B_ * FH_LDA; j += stride) { g_fhh[j] = bz; g_fhm[j] = bz; g_fhl[j] = bz; }
    for (int j = i; j < B_ * SH_LDA; j += stride) { g_shh[j] = bz; g_shm[j] = bz; g_shl[j] = bz; }
    for (int j = i; j < B_ * T_ * 4; j += stride) {
        size_t off = (size_t)(j >> 2) * HI_LDA + F_ + (j & 3);
        g_hih[off] = bz; g_him[off] = bz; g_hil[off] = bz;
    }
}

__global__ void tail_copy(float* __restrict__ out, size_t out_total)
{
    int i = blockIdx.x * blockDim.x + threadIdx.x;
    const size_t base = (size_t)B_ * T_ * V_;
    const int nF = B_ * F_, nS = B_ * S_;
    const int total = 2 * nF + 2 * nS;
    if (i >= total) return;
    float v;
    size_t off = base + i;
    if (i < nF)               v = g_fh[i];
    else if (i < 2 * nF)      v = g_fc[i - nF];
    else if (i < 2 * nF + nS) v = g_sh[i - 2 * nF];
    else                      v = g_sc[i - 2 * nF - nS];
    if (off < out_total) out[off] = v;
}

// ---------------------------------------------------------------------------
// Launch
// ---------------------------------------------------------------------------
extern "C" void kernel_launch(void* const* d_in, const int* in_sizes, int n_in,
                              void* d_out, int out_size)
{
    const float* inputs = (const float*)d_in[0];
    const float* W0  = (const float*)d_in[1];
    const float* b0  = (const float*)d_in[2];
    const float* g0  = (const float*)d_in[3];
    const float* bg0 = (const float*)d_in[4];
    const float* gc0 = (const float*)d_in[5];
    const float* bc0 = (const float*)d_in[6];
    const float* W1  = (const float*)d_in[7];
    const float* b1  = (const float*)d_in[8];
    const float* g1  = (const float*)d_in[9];
    const float* bg1 = (const float*)d_in[10];
    const float* gc1 = (const float*)d_in[11];
    const float* bc1 = (const float*)d_in[12];
    const float* WS  = (const float*)d_in[13];
    const float* bS  = (const float*)d_in[14];
    const float* gS  = (const float*)d_in[15];
    const float* bgS = (const float*)d_in[16];
    const float* gcS = (const float*)d_in[17];
    const float* bcS = (const float*)d_in[18];
    const float* Wout = (const float*)d_in[19];
    const float* bout = (const float*)d_in[20];
    float* out = (float*)d_out;

    RecParams P;
    float *z, *zS;
    bf16 *Woh, *Wom, *Wol, *hih, *him, *hil;
    cudaGetSymbolAddress((void**)&P.fh,  g_fh);  cudaGetSymbolAddress((void**)&P.fc,  g_fc);
    cudaGetSymbolAddress((void**)&P.sh,  g_sh);  cudaGetSymbolAddress((void**)&P.sc,  g_sc);
    cudaGetSymbolAddress((void**)&z,     g_z);   cudaGetSymbolAddress((void**)&zS,    g_zS);
    cudaGetSymbolAddress((void**)&P.xh,  g_xh);  cudaGetSymbolAddress((void**)&P.xm,  g_xm);
    cudaGetSymbolAddress((void**)&P.xl,  g_xl);
    cudaGetSymbolAddress((void**)&P.fhh, g_fhh); cudaGetSymbolAddress((void**)&P.fhm, g_fhm);
    cudaGetSymbolAddress((void**)&P.fhl, g_fhl);
    cudaGetSymbolAddress((void**)&P.shh, g_shh); cudaGetSymbolAddress((void**)&P.shm, g_shm);
    cudaGetSymbolAddress((void**)&P.shl, g_shl);
    cudaGetSymbolAddress((void**)&hih,   g_hih); cudaGetSymbolAddress((void**)&him,   g_him);
    cudaGetSymbolAddress((void**)&hil,   g_hil);
    cudaGetSymbolAddress((void**)&P.W0h, g_W0h); cudaGetSymbolAddress((void**)&P.W0m, g_W0m);
    cudaGetSymbolAddress((void**)&P.W0l, g_W0l);
    cudaGetSymbolAddress((void**)&P.WSh, g_WSh); cudaGetSymbolAddress((void**)&P.WSm, g_WSm);
    cudaGetSymbolAddress((void**)&P.WSl, g_WSl);
    cudaGetSymbolAddress((void**)&P.W1h, g_W1h); cudaGetSymbolAddress((void**)&P.W1m, g_W1m);
    cudaGetSymbolAddress((void**)&P.W1l, g_W1l);
    cudaGetSymbolAddress((void**)&Woh,   g_Woh); cudaGetSymbolAddress((void**)&Wom,   g_Wom);
    cudaGetSymbolAddress((void**)&Wol,   g_Wol);
    P.z = z; P.zS = zS;
    P.hih = hih; P.him = him; P.hil = hil;
    P.b0 = b0; P.g0 = g0; P.bg0 = bg0; P.gc0 = gc0; P.bc0 = bc0;
    P.b1 = b1; P.g1 = g1; P.bg1 = bg1; P.gc1 = gc1; P.bc1 = bc1;
    P.bS = bS; P.gS = gS; P.bgS = bgS; P.gcS = gcS; P.bcS = bcS;

    const int SMP  = 6 * ASZ + 6 * (64 * ARP);    // 92160 (persistent: GEMM worst case)
    const int SMPR = 4 * ASZ + 4 * (128 * ARP);   // 81920 (projection)
    cudaFuncSetAttribute(rec_persist, cudaFuncAttributeMaxDynamicSharedMemorySize, SMP);
    cudaFuncSetAttribute(gemm_proj,   cudaFuncAttributeMaxDynamicSharedMemorySize, SMPR);

    // Weight transpose + split
    {
        long n;
        n = (long)4 * F_ * 832;
        transpose_split<<<(unsigned)((n + 255) / 256), 256>>>(W0, (bf16*)P.W0h, (bf16*)P.W0m, (bf16*)P.W0l, 4 * F_, 832, 828, 0, 828);
        n = (long)4 * S_ * 1120;
        transpose_split<<<(unsigned)((n + 255) / 256), 256>>>(WS, (bf16*)P.WSh, (bf16*)P.WSm, (bf16*)P.WSl, 4 * S_, 1120, 700, 4, 1100);
        n = (long)4 * F_ * 1120;
        transpose_split<<<(unsigned)((n + 255) / 256), 256>>>(W1, (bf16*)P.W1h, (bf16*)P.W1m, (bf16*)P.W1l, 4 * F_, 1120, 1100, 0, 1100);
        n = (long)V_ * 704;
        transpose_split<<<(unsigned)((n + 255) / 256), 256>>>(Wout, Woh, Wom, Wol, V_, 704, 700, 0, 700);
    }
    {
        long n = (long)B_ * T_ * E_;
        split_inputs<<<(unsigned)((n + 255) / 256), 256>>>(inputs);
    }
    init_states<<<148, 256>>>();

    // Entire recurrence: ONE persistent kernel
    rec_persist<<<GRID_P, 256, SMP>>>(P);

    // Output projection: hist[12800,704] @ Wout^T + bias
    {
        const dim3 grid((V_ + 127) / 128, (B_ * T_) / 128, 1);   // 79 x 100
        gemm_proj<<<grid, 256, SMPR>>>(
            hih, him, HI_LDA, Woh, Wom, 704, bout, out, V_, V_, 704);
    }

    {
        int total = 2 * B_ * F_ + 2 * B_ * S_;
        tail_copy<<<(total + 255) / 256, 256>>>(out, (size_t)out_size);
    }
}

// round 11
// speedup vs baseline: 6.0656x; 1.2464x over previous
#include <cuda_runtime.h>
#include <cuda_fp16.h>
#include <cstdint>

// Problem constants
#define B_  128
#define T_  100
#define E_  128
#define F_  700
#define S_  400
#define V_  10000

#define FH_LDA 720
#define SH_LDA 424
#define HI_LDA 704

#define KS_CELL 3
#define KS_SLOW 5
#define GRID_P  132          // persistent grid (44*3)

typedef __half fp16;

// ---------------------------------------------------------------------------
// Static device scratch
// ---------------------------------------------------------------------------
__device__ float g_fh[B_ * F_];
__device__ float g_fc[B_ * F_];
__device__ float g_sh[B_ * S_];
__device__ float g_sc[B_ * S_];
__device__ float g_z [KS_CELL * B_ * 4 * F_];
__device__ float g_zS[KS_SLOW * B_ * 4 * S_];

__device__ fp16 g_xh[B_ * T_ * E_], g_xm[B_ * T_ * E_];
__device__ fp16 g_fhh[B_ * FH_LDA], g_fhm[B_ * FH_LDA];
__device__ fp16 g_shh[B_ * SH_LDA], g_shm[B_ * SH_LDA];
__device__ fp16 g_hih[(size_t)B_ * T_ * HI_LDA], g_him[(size_t)B_ * T_ * HI_LDA];

__device__ fp16 g_W0h[(size_t)4 * F_ * 832],  g_W0m[(size_t)4 * F_ * 832];
__device__ fp16 g_WSh[(size_t)4 * S_ * 1120], g_WSm[(size_t)4 * S_ * 1120];
__device__ fp16 g_W1h[(size_t)4 * F_ * 1120], g_W1m[(size_t)4 * F_ * 1120];
__device__ fp16 g_Woh[(size_t)V_ * 704],      g_Wom[(size_t)V_ * 704];

// Grid barrier state
__device__ unsigned g_barcnt;
__device__ unsigned g_bargen;

// ---------------------------------------------------------------------------
// Helpers
// ---------------------------------------------------------------------------
__device__ __forceinline__ uint32_t smem_u32(const void* p) {
    uint32_t a;
    asm("{ .reg .u64 t; cvta.to.shared.u64 t, %1; cvt.u32.u64 %0, t; }" : "=r"(a) : "l"(p));
    return a;
}
__device__ __forceinline__ void split2(float x, fp16& h, fp16& m) {
    h = __float2half_rn(x);
    m = __float2half_rn(x - __half2float(h));
}
__device__ __forceinline__ void mma_fp16(float c[4], const uint32_t a[4], const uint32_t b[2]) {
    asm volatile("mma.sync.aligned.m16n8k16.row.col.f32.f16.f16.f32 "
                 "{%0,%1,%2,%3}, {%4,%5,%6,%7}, {%8,%9}, {%0,%1,%2,%3};"
                 : "+f"(c[0]), "+f"(c[1]), "+f"(c[2]), "+f"(c[3])
                 : "r"(a[0]), "r"(a[1]), "r"(a[2]), "r"(a[3]), "r"(b[0]), "r"(b[1]));
}
#define CP16(dst, src, sz) \
    asm volatile("cp.async.cg.shared.global [%0], [%1], 16, %2;" \
                 :: "r"(dst), "l"(src), "r"(sz))
#define CP_COMMIT() asm volatile("cp.async.commit_group;" ::: "memory")
#define CP_WAIT1()  asm volatile("cp.async.wait_group 1;" ::: "memory")
#define CP_WAIT0()  asm volatile("cp.async.wait_group 0;" ::: "memory")

#define ARP   80
#define ASZ   (128 * ARP)            // 10240 bytes per A split-buffer

// ---------------------------------------------------------------------------
// Software grid barrier (all GRID_P CTAs co-resident; release/acquire).
// ---------------------------------------------------------------------------
__device__ __forceinline__ void gbar(unsigned& mygen) {
    __syncthreads();
    __threadfence();
    if (threadIdx.x == 0) {
        unsigned prev = atomicAdd(&g_barcnt, 1u);
        if (prev == (unsigned)(gridDim.x - 1)) {
            atomicExch(&g_barcnt, 0u);
            __threadfence();
            atomicAdd(&g_bargen, 1u);
        } else {
            volatile unsigned* vg = &g_bargen;
            while (*vg <= mygen) __nanosleep(128);
        }
    }
    mygen++;
    __syncthreads();
    __threadfence();
}

// ---------------------------------------------------------------------------
// GEMM phase (device fn), BN=64, fp16 2-way split, 3 products:
//   HM + MH chained in-MMA (|.| ~ 2^-11), H*H via zero-C MMA + IEEE FADD.
// Writes split-K partials (no bias). M = 128 fixed.
// ---------------------------------------------------------------------------
__device__ void gemm_phase(char* sm,
    const fp16* __restrict__ A1h, const fp16* __restrict__ A1m,
    int lda1, int K1p,
    const fp16* __restrict__ A2h, const fp16* __restrict__ A2m,
    int lda2,
    const fp16* __restrict__ Wh, const fp16* __restrict__ Wm,
    int ldw,
    float* __restrict__ C, int ldc, int pstride,
    int Kpad, int N, int tnc, int KS)
{
    constexpr int NT  = 4;
    constexpr int BSZ = 64 * ARP;             // 5120
    constexpr uint32_t BBASE = 4 * ASZ;       // 40960

    const int cta = blockIdx.x;
    if (cta >= tnc * KS) return;

    const uint32_t sbase = smem_u32(sm);
    const int tid  = threadIdx.x;
    const int wid  = tid >> 5;
    const int lane = tid & 31;
    const int wm   = wid & 3;
    const int wn   = wid >> 2;
    const int n0   = (cta % tnc) * 64;
    const int kz   = cta / tnc;
    const int nk   = Kpad >> 5;
    const int nkq  = (nk + KS - 1) / KS;
    const int i0   = kz * nkq;
    const int i1   = (i0 + nkq < nk) ? (i0 + nkq) : nk;

    const fp16* A1s[2] = {A1h, A1m};
    const fp16* A2s[2] = {A2h, A2m};
    const fp16* Ws [2] = {Wh,  Wm};

    float acc[2][NT][4], accs[2][NT][4];
    #pragma unroll
    for (int mt = 0; mt < 2; mt++)
        #pragma unroll
        for (int nt = 0; nt < NT; nt++)
            #pragma unroll
            for (int r = 0; r < 4; r++) { acc[mt][nt][r] = 0.0f; accs[mt][nt][r] = 0.0f; }

    auto load_chunk = [&](int i) {
        const int k0 = i << 5;
        const int buf = i & 1;
        #pragma unroll
        for (int it = 0; it < 4; it++) {
            const int sp  = it >> 1;
            const int idx = ((it & 1) << 8) + tid;
            const int r   = idx >> 2;
            const int c4  = idx & 3;
            const int gk  = k0 + (c4 << 3);
            const fp16* src = (gk < K1p) ? A1s[sp] + r * lda1 + gk
                                         : A2s[sp] + r * lda2 + (gk - K1p);
            CP16(sbase + sp * (2 * ASZ) + buf * ASZ + r * ARP + c4 * 16, src, 16);
        }
        #pragma unroll
        for (int it = 0; it < 2; it++) {
            const int sp  = it;
            const int r   = tid >> 2;
            const int c4  = tid & 3;
            const int n   = n0 + r;
            const int nc  = (n < N) ? n : (N - 1);
            const fp16* src = Ws[sp] + (long)nc * ldw + k0 + (c4 << 3);
            CP16(sbase + BBASE + sp * (2 * BSZ) + buf * BSZ + r * ARP + c4 * 16,
                 src, (n < N) ? 16 : 0);
        }
        CP_COMMIT();
    };

    if (i0 < i1) load_chunk(i0);
    for (int i = i0; i < i1; i++) {
        if (i + 1 < i1) { load_chunk(i + 1); CP_WAIT1(); }
        else            { CP_WAIT0(); }
        __syncthreads();
        const int buf = i & 1;

        #pragma unroll
        for (int ks = 0; ks < 2; ks++) {
            const uint32_t kb = (ks << 5) + ((lane & 3) << 2);
            uint32_t a[2][2][4];
            #pragma unroll
            for (int sp = 0; sp < 2; sp++)
                #pragma unroll
                for (int mt = 0; mt < 2; mt++) {
                    const char* base = sm + sp * (2 * ASZ) + buf * ASZ
                                     + (wm * 32 + mt * 16 + (lane >> 2)) * ARP + kb;
                    a[sp][mt][0] = *(const uint32_t*)(base);
                    a[sp][mt][1] = *(const uint32_t*)(base + 8 * ARP);
                    a[sp][mt][2] = *(const uint32_t*)(base + 16);
                    a[sp][mt][3] = *(const uint32_t*)(base + 8 * ARP + 16);
                }
            uint32_t b[2][NT][2];
            #pragma unroll
            for (int sp = 0; sp < 2; sp++)
                #pragma unroll
                for (int nt = 0; nt < NT; nt++) {
                    const char* base = sm + BBASE + sp * (2 * BSZ) + buf * BSZ
                                     + (wn * 32 + nt * 8 + (lane >> 2)) * ARP + kb;
                    b[sp][nt][0] = *(const uint32_t*)(base);
                    b[sp][nt][1] = *(const uint32_t*)(base + 16);
                }
            #pragma unroll
            for (int mt = 0; mt < 2; mt++)
                #pragma unroll
                for (int nt = 0; nt < NT; nt++) {
                    mma_fp16(accs[mt][nt], a[0][mt], b[1][nt]);  // H*M (~2^-11)
                    mma_fp16(accs[mt][nt], a[1][mt], b[0][nt]);  // M*H (~2^-11)
                    float d[4] = {0.f, 0.f, 0.f, 0.f};           // H*H unchained
                    mma_fp16(d, a[0][mt], b[0][nt]);
                    acc[mt][nt][0] += d[0];
                    acc[mt][nt][1] += d[1];
                    acc[mt][nt][2] += d[2];
                    acc[mt][nt][3] += d[3];
                }
        }
        __syncthreads();
    }

    float* Cp = C + (size_t)kz * pstride;
    #pragma unroll
    for (int mt = 0; mt < 2; mt++) {
        int gm = wm * 32 + mt * 16 + (lane >> 2);
        #pragma unroll
        for (int nt = 0; nt < NT; nt++) {
            int gn = n0 + wn * 32 + nt * 8 + ((lane & 3) << 1);
            if (gn < N) {
                float r0 = acc[mt][nt][0] + accs[mt][nt][0];
                float r1 = acc[mt][nt][1] + accs[mt][nt][1];
                float r2 = acc[mt][nt][2] + accs[mt][nt][2];
                float r3 = acc[mt][nt][3] + accs[mt][nt][3];
                *(float2*)(Cp + (size_t)gm * ldc + gn)       = make_float2(r0, r1);
                *(float2*)(Cp + (size_t)(gm + 8) * ldc + gn) = make_float2(r2, r3);
            }
        }
    }
}

// ---------------------------------------------------------------------------
// Pointwise phase (device fn). z partials read with __ldcg (L1 bypass).
// ---------------------------------------------------------------------------
__device__ __forceinline__ float sigm(float x) { return 1.0f / (1.0f + __expf(-x)); }

__device__ __forceinline__ float blockReduceSum(float v, float* red) {
    int lane = threadIdx.x & 31;
    int w    = threadIdx.x >> 5;
    #pragma unroll
    for (int o = 16; o > 0; o >>= 1) v += __shfl_down_sync(0xffffffffu, v, o);
    if (lane == 0) red[w] = v;
    __syncthreads();
    float r = 0.0f;
    if (w == 0) {
        int nw = blockDim.x >> 5;
        r = (lane < nw) ? red[lane] : 0.0f;
        #pragma unroll
        for (int o = 16; o > 0; o >>= 1) r += __shfl_down_sync(0xffffffffu, r, o);
        if (lane == 0) red[0] = r;
    }
    __syncthreads();
    r = red[0];
    __syncthreads();
    return r;
}

__device__ void pw_phase(char* smraw,
    const float* __restrict__ zp, int pstride, int nparts,
    const float* __restrict__ bias,
    float* __restrict__ h, float* __restrict__ c, int H,
    const float* __restrict__ gg, const float* __restrict__ bg,
    const float* __restrict__ gc, const float* __restrict__ bc,
    fp16* __restrict__ sph, fp16* __restrict__ spm, int sp_lda,
    fp16* __restrict__ hih, fp16* __restrict__ him, int t)
{
    const int b = blockIdx.x;
    if (b >= B_) return;
    float* zs  = (float*)smraw;          // 4*H floats
    float* red = zs + 4 * F_;            // 32 floats
    const float invH = 1.0f / (float)H;
    const size_t rowoff = (size_t)b * 4 * H;

    float s[4] = {0, 0, 0, 0}, q[4] = {0, 0, 0, 0};
    for (int u = threadIdx.x; u < H; u += blockDim.x) {
        #pragma unroll
        for (int ch = 0; ch < 4; ch++) {
            const int off = ch * H + u;
            float v = bias[off];
            for (int p = 0; p < nparts; p++)
                v += __ldcg(zp + (size_t)p * pstride + rowoff + off);
            zs[off] = v;
            s[ch] += v;
            q[ch] += v * v;
        }
    }
    __syncthreads();

    float mu[4], rs[4];
    #pragma unroll
    for (int ch = 0; ch < 4; ch++) {
        float smv = blockReduceSum(s[ch], red);
        float sq  = blockReduceSum(q[ch], red);
        mu[ch] = smv * invH;
        float var = sq * invH - mu[ch] * mu[ch];
        rs[ch] = rsqrtf(var + 1e-5f);
    }

    float nc_r[3], so_r[3];
    float sc_acc = 0.0f, qc_acc = 0.0f;
    #pragma unroll
    for (int it = 0; it < 3; it++) {
        int u = threadIdx.x + it * 256;
        if (u < H) {
            float iv = (zs[0 * H + u] - mu[0]) * rs[0] * gg[0 * H + u] + bg[0 * H + u];
            float jv = (zs[1 * H + u] - mu[1]) * rs[1] * gg[1 * H + u] + bg[1 * H + u];
            float fv = (zs[2 * H + u] - mu[2]) * rs[2] * gg[2 * H + u] + bg[2 * H + u];
            float ov = (zs[3 * H + u] - mu[3]) * rs[3] * gg[3 * H + u] + bg[3 * H + u];
            float cold = c[(size_t)b * H + u];
            float nc = cold * sigm(fv + 1.0f) + sigm(iv) * tanhf(jv);
            nc_r[it] = nc;
            so_r[it] = sigm(ov);
            sc_acc += nc;
            qc_acc += nc * nc;
        }
    }
    float smc = blockReduceSum(sc_acc, red);
    float sqc = blockReduceSum(qc_acc, red);
    float muc = smc * invH;
    float rsc = rsqrtf(sqc * invH - muc * muc + 1e-5f);

    #pragma unroll
    for (int it = 0; it < 3; it++) {
        int u = threadIdx.x + it * 256;
        if (u < H) {
            float nc = nc_r[it];
            float nh = tanhf((nc - muc) * rsc * gc[u] + bc[u]) * so_r[it];
            float hold = h[(size_t)b * H + u];
            float cold = c[(size_t)b * H + u];
            float hn = 0.9f * nh + 0.1f * hold;
            float cn = 0.5f * nc + 0.5f * cold;
            h[(size_t)b * H + u] = hn;
            c[(size_t)b * H + u] = cn;
            fp16 sh_, sm_;
            split2(hn, sh_, sm_);
            size_t so = (size_t)b * sp_lda + u;
            sph[so] = sh_; spm[so] = sm_;
            if (hih) {
                size_t ho = ((size_t)b * T_ + t) * HI_LDA + u;
                hih[ho] = sh_; him[ho] = sm_;
            }
        }
    }
}

// ---------------------------------------------------------------------------
// Persistent recurrence kernel: 100 steps x 6 phases, software grid barriers.
// ---------------------------------------------------------------------------
struct RecParams {
    const fp16 *xh, *xm;
    const float *b0, *g0, *bg0, *gc0, *bc0;
    const float *bS, *gS, *bgS, *gcS, *bcS;
    const float *b1, *g1, *bg1, *gc1, *bc1;
    const fp16 *W0h, *W0m, *WSh, *WSm, *W1h, *W1m;
    float *fh, *fc, *sh, *sc, *z, *zS;
    fp16 *fhh, *fhm, *shh, *shm, *hih, *him;
};

__global__ void __launch_bounds__(256)
rec_persist(RecParams P)
{
    extern __shared__ char sm[];
    unsigned mygen = 0;
    const int psC = B_ * 4 * F_;
    const int psS = B_ * 4 * S_;

    for (int t = 0; t < T_; t++) {
        // Fast cell 0: A = [x_t | fh], Kpad=832, K1p=128
        gemm_phase(sm, P.xh + t * E_, P.xm + t * E_, T_ * E_, 128,
                   P.fhh, P.fhm, FH_LDA,
                   P.W0h, P.W0m, 832,
                   P.z, 4 * F_, psC, 832, 4 * F_, 44, KS_CELL);
        gbar(mygen);
        pw_phase(sm, P.z, psC, KS_CELL, P.b0, P.fh, P.fc, F_,
                 P.g0, P.bg0, P.gc0, P.bc0,
                 P.fhh, P.fhm, FH_LDA, nullptr, nullptr, 0);
        gbar(mygen);

        // Slow cell: A = [fh | gap4 | sh], Kpad=1120, K1p=704
        gemm_phase(sm, P.fhh, P.fhm, FH_LDA, 704,
                   P.shh, P.shm, SH_LDA,
                   P.WSh, P.WSm, 1120,
                   P.zS, 4 * S_, psS, 1120, 4 * S_, 25, KS_SLOW);
        gbar(mygen);
        pw_phase(sm, P.zS, psS, KS_SLOW, P.bS, P.sh, P.sc, S_,
                 P.gS, P.bgS, P.gcS, P.bcS,
                 P.shh, P.shm, SH_LDA, nullptr, nullptr, 0);
        gbar(mygen);

        // Fast cell 1: A = [sh | fh], Kpad=1120, K1p=400
        gemm_phase(sm, P.shh, P.shm, SH_LDA, 400,
                   P.fhh, P.fhm, FH_LDA,
                   P.W1h, P.W1m, 1120,
                   P.z, 4 * F_, psC, 1120, 4 * F_, 44, KS_CELL);
        gbar(mygen);
        pw_phase(sm, P.z, psC, KS_CELL, P.b1, P.fh, P.fc, F_,
                 P.g1, P.bg1, P.gc1, P.bc1,
                 P.fhh, P.fhm, FH_LDA, P.hih, P.him, t);
        gbar(mygen);
    }
}

// ---------------------------------------------------------------------------
// Projection GEMM kernel (fp16 x3: HH + HM + MH chained, bias) — BN=128.
// ---------------------------------------------------------------------------
__global__ void __launch_bounds__(256)
gemm_proj(const fp16* __restrict__ Ah, const fp16* __restrict__ Am, long lda,
          const fp16* __restrict__ Wh, const fp16* __restrict__ Wm, int ldw,
          const float* __restrict__ bias,
          float* __restrict__ C, long ldc, int N, int Kpad)
{
    constexpr int NT  = 8;
    constexpr int BSZ = 128 * ARP;            // 10240
    constexpr uint32_t BBASE = 4 * ASZ;       // 40960

    extern __shared__ char sm[];
    const uint32_t sbase = smem_u32(sm);
    const int tid  = threadIdx.x;
    const int wid  = tid >> 5;
    const int lane = tid & 31;
    const int wm   = wid & 3;
    const int wn   = wid >> 2;
    const int n0   = blockIdx.x * 128;
    const long m0  = (long)blockIdx.y * 128;
    const int nk   = Kpad >> 5;

    const fp16* As[2] = {Ah, Am};
    const fp16* Ws[2] = {Wh, Wm};

    float acc[2][NT][4];
    #pragma unroll
    for (int mt = 0; mt < 2; mt++)
        #pragma unroll
        for (int nt = 0; nt < NT; nt++)
            #pragma unroll
            for (int r = 0; r < 4; r++) acc[mt][nt][r] = 0.0f;

    auto load_chunk = [&](int i) {
        const int k0 = i << 5;
        const int buf = i & 1;
        #pragma unroll
        for (int it = 0; it < 4; it++) {
            const int sp  = it >> 1;
            const int idx = ((it & 1) << 8) + tid;
            const int r   = idx >> 2;
            const int c4  = idx & 3;
            CP16(sbase + sp * (2 * ASZ) + buf * ASZ + r * ARP + c4 * 16,
                 As[sp] + (m0 + r) * lda + k0 + (c4 << 3), 16);
        }
        #pragma unroll
        for (int it = 0; it < 4; it++) {
            const int sp  = it >> 1;
            const int idx = ((it & 1) << 8) + tid;
            const int r   = idx >> 2;
            const int c4  = idx & 3;
            const int n   = n0 + r;
            const int nc  = (n < N) ? n : (N - 1);
            CP16(sbase + BBASE + sp * (2 * BSZ) + buf * BSZ + r * ARP + c4 * 16,
                 Ws[sp] + (long)nc * ldw + k0 + (c4 << 3), (n < N) ? 16 : 0);
        }
        CP_COMMIT();
    };

    load_chunk(0);
    for (int i = 0; i < nk; i++) {
        if (i + 1 < nk) { load_chunk(i + 1); CP_WAIT1(); }
        else            { CP_WAIT0(); }
        __syncthreads();
        const int buf = i & 1;

        #pragma unroll
        for (int ks = 0; ks < 2; ks++) {
            const uint32_t kb = (ks << 5) + ((lane & 3) << 2);
            uint32_t a[2][2][4];
            #pragma unroll
            for (int sp = 0; sp < 2; sp++)
                #pragma unroll
                for (int mt = 0; mt < 2; mt++) {
                    const char* base = sm + sp * (2 * ASZ) + buf * ASZ
                                     + (wm * 32 + mt * 16 + (lane >> 2)) * ARP + kb;
                    a[sp][mt][0] = *(const uint32_t*)(base);
                    a[sp][mt][1] = *(const uint32_t*)(base + 8 * ARP);
                    a[sp][mt][2] = *(const uint32_t*)(base + 16);
                    a[sp][mt][3] = *(const uint32_t*)(base + 8 * ARP + 16);
                }
            uint32_t b[2][NT][2];
            #pragma unroll
            for (int sp = 0; sp < 2; sp++)
                #pragma unroll
                for (int nt = 0; nt < NT; nt++) {
                    const char* base = sm + BBASE + sp * (2 * BSZ) + buf * BSZ
                                     + (wn * 64 + nt * 8 + (lane >> 2)) * ARP + kb;
                    b[sp][nt][0] = *(const uint32_t*)(base);
                    b[sp][nt][1] = *(const uint32_t*)(base + 16);
                }
            #pragma unroll
            for (int mt = 0; mt < 2; mt++)
                #pragma unroll
                for (int nt = 0; nt < NT; nt++) {
                    mma_fp16(acc[mt][nt], a[0][mt], b[1][nt]);  // H*M
                    mma_fp16(acc[mt][nt], a[1][mt], b[0][nt]);  // M*H
                    mma_fp16(acc[mt][nt], a[0][mt], b[0][nt]);  // H*H
                }
        }
        __syncthreads();
    }

    #pragma unroll
    for (int mt = 0; mt < 2; mt++) {
        long gm = m0 + wm * 32 + mt * 16 + (lane >> 2);
        #pragma unroll
        for (int nt = 0; nt < NT; nt++) {
            int gn = n0 + wn * 64 + nt * 8 + ((lane & 3) << 1);
            if (gn < N) {
                float2 bv = *(const float2*)(bias + gn);
                *(float2*)(C + gm * ldc + gn) =
                    make_float2(acc[mt][nt][0] + bv.x, acc[mt][nt][1] + bv.y);
                *(float2*)(C + (gm + 8) * ldc + gn) =
                    make_float2(acc[mt][nt][2] + bv.x, acc[mt][nt][3] + bv.y);
            }
        }
    }
}

// ---------------------------------------------------------------------------
// Setup kernels
// ---------------------------------------------------------------------------
__global__ void transpose_split(const float* __restrict__ in,
                                fp16* __restrict__ oh, fp16* __restrict__ om,
                                int N, int ldw, int K1, int gap, int Ktot)
{
    long idx = (long)blockIdx.x * blockDim.x + threadIdx.x;
    long total = (long)N * ldw;
    if (idx >= total) return;
    int n = (int)(idx / ldw);
    int k = (int)(idx % ldw);
    float v = 0.0f;
    if (k < K1)                               v = in[(long)k * N + n];
    else if (k >= K1 + gap && k < Ktot + gap) v = in[(long)(k - gap) * N + n];
    fp16 h, m;
    split2(v, h, m);
    oh[idx] = h; om[idx] = m;
}

__global__ void split_inputs(const float* __restrict__ in)
{
    long idx = (long)blockIdx.x * blockDim.x + threadIdx.x;
    if (idx >= (long)B_ * T_ * E_) return;
    fp16 h, m;
    split2(in[idx], h, m);
    g_xh[idx] = h; g_xm[idx] = m;
}

__global__ void init_states()
{
    int i = blockIdx.x * blockDim.x + threadIdx.x;
    int stride = gridDim.x * blockDim.x;
    const fp16 hz = __float2half(0.0f);
    if (i == 0) { g_barcnt = 0u; g_bargen = 0u; }
    for (int j = i; j < B_ * F_; j += stride) { g_fh[j] = 0.0f; g_fc[j] = 0.0f; }
    for (int j = i; j < B_ * S_; j += stride) { g_sh[j] = 0.0f; g_sc[j] = 0.0f; }
    for (int j = i; j < B_ * FH_LDA; j += stride) { g_fhh[j] = hz; g_fhm[j] = hz; }
    for (int j = i; j < B_ * SH_LDA; j += stride) { g_shh[j] = hz; g_shm[j] = hz; }
    for (int j = i; j < B_ * T_ * 4; j += stride) {
        size_t off = (size_t)(j >> 2) * HI_LDA + F_ + (j & 3);
        g_hih[off] = hz; g_him[off] = hz;
    }
}

__global__ void tail_copy(float* __restrict__ out, size_t out_total)
{
    int i = blockIdx.x * blockDim.x + threadIdx.x;
    const size_t base = (size_t)B_ * T_ * V_;
    const int nF = B_ * F_, nS = B_ * S_;
    const int total = 2 * nF + 2 * nS;
    if (i >= total) return;
    float v;
    size_t off = base + i;
    if (i < nF)               v = g_fh[i];
    else if (i < 2 * nF)      v = g_fc[i - nF];
    else if (i < 2 * nF + nS) v = g_sh[i - 2 * nF];
    else                      v = g_sc[i - 2 * nF - nS];
    if (off < out_total) out[off] = v;
}

// ---------------------------------------------------------------------------
// Launch
// ---------------------------------------------------------------------------
extern "C" void kernel_launch(void* const* d_in, const int* in_sizes, int n_in,
                              void* d_out, int out_size)
{
    const float* inputs = (const float*)d_in[0];
    const float* W0  = (const float*)d_in[1];
    const float* b0  = (const float*)d_in[2];
    const float* g0  = (const float*)d_in[3];
    const float* bg0 = (const float*)d_in[4];
    const float* gc0 = (const float*)d_in[5];
    const float* bc0 = (const float*)d_in[6];
    const float* W1  = (const float*)d_in[7];
    const float* b1  = (const float*)d_in[8];
    const float* g1  = (const float*)d_in[9];
    const float* bg1 = (const float*)d_in[10];
    const float* gc1 = (const float*)d_in[11];
    const float* bc1 = (const float*)d_in[12];
    const float* WS  = (const float*)d_in[13];
    const float* bS  = (const float*)d_in[14];
    const float* gS  = (const float*)d_in[15];
    const float* bgS = (const float*)d_in[16];
    const float* gcS = (const float*)d_in[17];
    const float* bcS = (const float*)d_in[18];
    const float* Wout = (const float*)d_in[19];
    const float* bout = (const float*)d_in[20];
    float* out = (float*)d_out;

    RecParams P;
    float *z, *zS;
    fp16 *Woh, *Wom, *hih, *him;
    cudaGetSymbolAddress((void**)&P.fh,  g_fh);  cudaGetSymbolAddress((void**)&P.fc,  g_fc);
    cudaGetSymbolAddress((void**)&P.sh,  g_sh);  cudaGetSymbolAddress((void**)&P.sc,  g_sc);
    cudaGetSymbolAddress((void**)&z,     g_z);   cudaGetSymbolAddress((void**)&zS,    g_zS);
    cudaGetSymbolAddress((void**)&P.xh,  g_xh);  cudaGetSymbolAddress((void**)&P.xm,  g_xm);
    cudaGetSymbolAddress((void**)&P.fhh, g_fhh); cudaGetSymbolAddress((void**)&P.fhm, g_fhm);
    cudaGetSymbolAddress((void**)&P.shh, g_shh); cudaGetSymbolAddress((void**)&P.shm, g_shm);
    cudaGetSymbolAddress((void**)&hih,   g_hih); cudaGetSymbolAddress((void**)&him,   g_him);
    cudaGetSymbolAddress((void**)&P.W0h, g_W0h); cudaGetSymbolAddress((void**)&P.W0m, g_W0m);
    cudaGetSymbolAddress((void**)&P.WSh, g_WSh); cudaGetSymbolAddress((void**)&P.WSm, g_WSm);
    cudaGetSymbolAddress((void**)&P.W1h, g_W1h); cudaGetSymbolAddress((void**)&P.W1m, g_W1m);
    cudaGetSymbolAddress((void**)&Woh,   g_Woh); cudaGetSymbolAddress((void**)&Wom,   g_Wom);
    P.z = z; P.zS = zS;
    P.hih = hih; P.him = him;
    P.b0 = b0; P.g0 = g0; P.bg0 = bg0; P.gc0 = gc0; P.bc0 = bc0;
    P.b1 = b1; P.g1 = g1; P.bg1 = bg1; P.gc1 = gc1; P.bc1 = bc1;
    P.bS = bS; P.gS = gS; P.bgS = bgS; P.gcS = gcS; P.bcS = bcS;

    const int SMP  = 4 * ASZ + 4 * (64 * ARP);    // 61440 (persistent)
    const int SMPR = 4 * ASZ + 4 * (128 * ARP);   // 81920 (projection)
    cudaFuncSetAttribute(rec_persist, cudaFuncAttributeMaxDynamicSharedMemorySize, SMP);
    cudaFuncSetAttribute(gemm_proj,   cudaFuncAttributeMaxDynamicSharedMemorySize, SMPR);

    // Weight transpose + split
    {
        long n;
        n = (long)4 * F_ * 832;
        transpose_split<<<(unsigned)((n + 255) / 256), 256>>>(W0, (fp16*)P.W0h, (fp16*)P.W0m, 4 * F_, 832, 828, 0, 828);
        n = (long)4 * S_ * 1120;
        transpose_split<<<(unsigned)((n + 255) / 256), 256>>>(WS, (fp16*)P.WSh, (fp16*)P.WSm, 4 * S_, 1120, 700, 4, 1100);
        n = (long)4 * F_ * 1120;
        transpose_split<<<(unsigned)((n + 255) / 256), 256>>>(W1, (fp16*)P.W1h, (fp16*)P.W1m, 4 * F_, 1120, 1100, 0, 1100);
        n = (long)V_ * 704;
        transpose_split<<<(unsigned)((n + 255) / 256), 256>>>(Wout, Woh, Wom, V_, 704, 700, 0, 700);
    }
    {
        long n = (long)B_ * T_ * E_;
        split_inputs<<<(unsigned)((n + 255) / 256), 256>>>(inputs);
    }
    init_states<<<148, 256>>>();

    // Entire recurrence: ONE persistent kernel
    rec_persist<<<GRID_P, 256, SMP>>>(P);

    // Output projection: hist[12800,704] @ Wout^T + bias
    {
        const dim3 grid((V_ + 127) / 128, (B_ * T_) / 128, 1);   // 79 x 100
        gemm_proj<<<grid, 256, SMPR>>>(
            hih, him, HI_LDA, Woh, Wom, 704, bout, out, V_, V_, 704);
    }

    {
        int total = 2 * B_ * F_ + 2 * B_ * S_;
        tail_copy<<<(total + 255) / 256, 256>>>(out, (size_t)out_size);
    }
}

// round 12
// speedup vs baseline: 6.4602x; 1.0651x over previous
#include <cuda_runtime.h>
#include <cuda_fp16.h>
#include <cstdint>

// Problem constants
#define B_  128
#define T_  100
#define E_  128
#define F_  700
#define S_  400
#define V_  10000

#define FH_LDA 720
#define SH_LDA 424
#define HI_LDA 704

#define KS_CELL 3
#define KS_SLOW 5
#define GRID_P  132          // persistent grid (44*3)

typedef __half fp16;

// ---------------------------------------------------------------------------
// Static device scratch
// ---------------------------------------------------------------------------
__device__ float g_fh[B_ * F_];
__device__ float g_fc[B_ * F_];
__device__ float g_sh[B_ * S_];
__device__ float g_sc[B_ * S_];
__device__ float g_z [KS_CELL * B_ * 4 * F_];
__device__ float g_zS[KS_SLOW * B_ * 4 * S_];

__device__ fp16 g_xh[B_ * T_ * E_], g_xm[B_ * T_ * E_];
__device__ fp16 g_fhh[B_ * FH_LDA], g_fhm[B_ * FH_LDA];
__device__ fp16 g_shh[B_ * SH_LDA], g_shm[B_ * SH_LDA];
__device__ fp16 g_hih[(size_t)B_ * T_ * HI_LDA];          // hist high split only

__device__ fp16 g_W0h[(size_t)4 * F_ * 832],  g_W0m[(size_t)4 * F_ * 832];
__device__ fp16 g_WSh[(size_t)4 * S_ * 1120], g_WSm[(size_t)4 * S_ * 1120];
__device__ fp16 g_W1h[(size_t)4 * F_ * 1120], g_W1m[(size_t)4 * F_ * 1120];
__device__ fp16 g_Woh[(size_t)V_ * 704],      g_Wom[(size_t)V_ * 704];

// Grid barrier state: per-CTA arrival flags (32B stride) + release word
__device__ unsigned g_flags[GRID_P * 8];
__device__ unsigned g_bargen;

// ---------------------------------------------------------------------------
// Helpers
// ---------------------------------------------------------------------------
__device__ __forceinline__ uint32_t smem_u32(const void* p) {
    uint32_t a;
    asm("{ .reg .u64 t; cvta.to.shared.u64 t, %1; cvt.u32.u64 %0, t; }" : "=r"(a) : "l"(p));
    return a;
}
__device__ __forceinline__ void split2(float x, fp16& h, fp16& m) {
    h = __float2half_rn(x);
    m = __float2half_rn(x - __half2float(h));
}
__device__ __forceinline__ void mma_fp16(float c[4], const uint32_t a[4], const uint32_t b[2]) {
    asm volatile("mma.sync.aligned.m16n8k16.row.col.f32.f16.f16.f32 "
                 "{%0,%1,%2,%3}, {%4,%5,%6,%7}, {%8,%9}, {%0,%1,%2,%3};"
                 : "+f"(c[0]), "+f"(c[1]), "+f"(c[2]), "+f"(c[3])
                 : "r"(a[0]), "r"(a[1]), "r"(a[2]), "r"(a[3]), "r"(b[0]), "r"(b[1]));
}
#define CP16(dst, src, sz) \
    asm volatile("cp.async.cg.shared.global [%0], [%1], 16, %2;" \
                 :: "r"(dst), "l"(src), "r"(sz))
#define CP_COMMIT() asm volatile("cp.async.commit_group;" ::: "memory")
#define CP_WAIT1()  asm volatile("cp.async.wait_group 1;" ::: "memory")
#define CP_WAIT0()  asm volatile("cp.async.wait_group 0;" ::: "memory")

#define ARP   80
#define ASZ   (128 * ARP)            // 10240 bytes per A split-buffer

// ---------------------------------------------------------------------------
// Fast grid barrier: parallel flag stores + CTA0 gather + single release word.
// Flags/generation are monotone; no resets mid-kernel (reset on replay).
// ---------------------------------------------------------------------------
__device__ __forceinline__ void gbar(unsigned& mygen) {
    mygen++;
    __syncthreads();
    __threadfence();
    if (threadIdx.x == 0)
        *((volatile unsigned*)&g_flags[blockIdx.x * 8]) = mygen;
    if (blockIdx.x == 0) {
        if (threadIdx.x < GRID_P) {
            volatile unsigned* f = &g_flags[threadIdx.x * 8];
            while (*f < mygen) {}
        }
        __syncthreads();
        if (threadIdx.x == 0) {
            __threadfence();
            *((volatile unsigned*)&g_bargen) = mygen;
        }
    } else {
        if (threadIdx.x == 0) {
            volatile unsigned* g = &g_bargen;
            while (*g < mygen) {}
        }
    }
    __syncthreads();
    __threadfence();
}

// ---------------------------------------------------------------------------
// GEMM phase (device fn), BN=64, fp16 2-way split, 3 products:
//   HM + MH chained in-MMA (|.| ~ 2^-11), H*H via zero-C MMA + IEEE FADD.
// Writes split-K partials (no bias). M = 128 fixed.
// ---------------------------------------------------------------------------
__device__ void gemm_phase(char* sm,
    const fp16* __restrict__ A1h, const fp16* __restrict__ A1m,
    int lda1, int K1p,
    const fp16* __restrict__ A2h, const fp16* __restrict__ A2m,
    int lda2,
    const fp16* __restrict__ Wh, const fp16* __restrict__ Wm,
    int ldw,
    float* __restrict__ C, int ldc, int pstride,
    int Kpad, int N, int tnc, int KS)
{
    constexpr int NT  = 4;
    constexpr int BSZ = 64 * ARP;             // 5120
    constexpr uint32_t BBASE = 4 * ASZ;       // 40960

    const int cta = blockIdx.x;
    if (cta >= tnc * KS) return;

    const uint32_t sbase = smem_u32(sm);
    const int tid  = threadIdx.x;
    const int wid  = tid >> 5;
    const int lane = tid & 31;
    const int wm   = wid & 3;
    const int wn   = wid >> 2;
    const int n0   = (cta % tnc) * 64;
    const int kz   = cta / tnc;
    const int nk   = Kpad >> 5;
    const int nkq  = (nk + KS - 1) / KS;
    const int i0   = kz * nkq;
    const int i1   = (i0 + nkq < nk) ? (i0 + nkq) : nk;

    const fp16* A1s[2] = {A1h, A1m};
    const fp16* A2s[2] = {A2h, A2m};
    const fp16* Ws [2] = {Wh,  Wm};

    float acc[2][NT][4], accs[2][NT][4];
    #pragma unroll
    for (int mt = 0; mt < 2; mt++)
        #pragma unroll
        for (int nt = 0; nt < NT; nt++)
            #pragma unroll
            for (int r = 0; r < 4; r++) { acc[mt][nt][r] = 0.0f; accs[mt][nt][r] = 0.0f; }

    auto load_chunk = [&](int i) {
        const int k0 = i << 5;
        const int buf = i & 1;
        #pragma unroll
        for (int it = 0; it < 4; it++) {
            const int sp  = it >> 1;
            const int idx = ((it & 1) << 8) + tid;
            const int r   = idx >> 2;
            const int c4  = idx & 3;
            const int gk  = k0 + (c4 << 3);
            const fp16* src = (gk < K1p) ? A1s[sp] + r * lda1 + gk
                                         : A2s[sp] + r * lda2 + (gk - K1p);
            CP16(sbase + sp * (2 * ASZ) + buf * ASZ + r * ARP + c4 * 16, src, 16);
        }
        #pragma unroll
        for (int it = 0; it < 2; it++) {
            const int sp  = it;
            const int r   = tid >> 2;
            const int c4  = tid & 3;
            const int n   = n0 + r;
            const int nc  = (n < N) ? n : (N - 1);
            const fp16* src = Ws[sp] + (long)nc * ldw + k0 + (c4 << 3);
            CP16(sbase + BBASE + sp * (2 * BSZ) + buf * BSZ + r * ARP + c4 * 16,
                 src, (n < N) ? 16 : 0);
        }
        CP_COMMIT();
    };

    if (i0 < i1) load_chunk(i0);
    for (int i = i0; i < i1; i++) {
        if (i + 1 < i1) { load_chunk(i + 1); CP_WAIT1(); }
        else            { CP_WAIT0(); }
        __syncthreads();
        const int buf = i & 1;

        #pragma unroll
        for (int ks = 0; ks < 2; ks++) {
            const uint32_t kb = (ks << 5) + ((lane & 3) << 2);
            uint32_t a[2][2][4];
            #pragma unroll
            for (int sp = 0; sp < 2; sp++)
                #pragma unroll
                for (int mt = 0; mt < 2; mt++) {
                    const char* base = sm + sp * (2 * ASZ) + buf * ASZ
                                     + (wm * 32 + mt * 16 + (lane >> 2)) * ARP + kb;
                    a[sp][mt][0] = *(const uint32_t*)(base);
                    a[sp][mt][1] = *(const uint32_t*)(base + 8 * ARP);
                    a[sp][mt][2] = *(const uint32_t*)(base + 16);
                    a[sp][mt][3] = *(const uint32_t*)(base + 8 * ARP + 16);
                }
            uint32_t b[2][NT][2];
            #pragma unroll
            for (int sp = 0; sp < 2; sp++)
                #pragma unroll
                for (int nt = 0; nt < NT; nt++) {
                    const char* base = sm + BBASE + sp * (2 * BSZ) + buf * BSZ
                                     + (wn * 32 + nt * 8 + (lane >> 2)) * ARP + kb;
                    b[sp][nt][0] = *(const uint32_t*)(base);
                    b[sp][nt][1] = *(const uint32_t*)(base + 16);
                }
            #pragma unroll
            for (int mt = 0; mt < 2; mt++)
                #pragma unroll
                for (int nt = 0; nt < NT; nt++) {
                    mma_fp16(accs[mt][nt], a[0][mt], b[1][nt]);  // H*M (~2^-11)
                    mma_fp16(accs[mt][nt], a[1][mt], b[0][nt]);  // M*H (~2^-11)
                    float d[4] = {0.f, 0.f, 0.f, 0.f};           // H*H unchained
                    mma_fp16(d, a[0][mt], b[0][nt]);
                    acc[mt][nt][0] += d[0];
                    acc[mt][nt][1] += d[1];
                    acc[mt][nt][2] += d[2];
                    acc[mt][nt][3] += d[3];
                }
        }
        __syncthreads();
    }

    float* Cp = C + (size_t)kz * pstride;
    #pragma unroll
    for (int mt = 0; mt < 2; mt++) {
        int gm = wm * 32 + mt * 16 + (lane >> 2);
        #pragma unroll
        for (int nt = 0; nt < NT; nt++) {
            int gn = n0 + wn * 32 + nt * 8 + ((lane & 3) << 1);
            if (gn < N) {
                float r0 = acc[mt][nt][0] + accs[mt][nt][0];
                float r1 = acc[mt][nt][1] + accs[mt][nt][1];
                float r2 = acc[mt][nt][2] + accs[mt][nt][2];
                float r3 = acc[mt][nt][3] + accs[mt][nt][3];
                *(float2*)(Cp + (size_t)gm * ldc + gn)       = make_float2(r0, r1);
                *(float2*)(Cp + (size_t)(gm + 8) * ldc + gn) = make_float2(r2, r3);
            }
        }
    }
}

// ---------------------------------------------------------------------------
// Pointwise phase (device fn). z partials read with __ldcg (L1 bypass).
// ---------------------------------------------------------------------------
__device__ __forceinline__ float sigm(float x) { return 1.0f / (1.0f + __expf(-x)); }

__device__ __forceinline__ float blockReduceSum(float v, float* red) {
    int lane = threadIdx.x & 31;
    int w    = threadIdx.x >> 5;
    #pragma unroll
    for (int o = 16; o > 0; o >>= 1) v += __shfl_down_sync(0xffffffffu, v, o);
    if (lane == 0) red[w] = v;
    __syncthreads();
    float r = 0.0f;
    if (w == 0) {
        int nw = blockDim.x >> 5;
        r = (lane < nw) ? red[lane] : 0.0f;
        #pragma unroll
        for (int o = 16; o > 0; o >>= 1) r += __shfl_down_sync(0xffffffffu, r, o);
        if (lane == 0) red[0] = r;
    }
    __syncthreads();
    r = red[0];
    __syncthreads();
    return r;
}

__device__ void pw_phase(char* smraw,
    const float* __restrict__ zp, int pstride, int nparts,
    const float* __restrict__ bias,
    float* __restrict__ h, float* __restrict__ c, int H,
    const float* __restrict__ gg, const float* __restrict__ bg,
    const float* __restrict__ gc, const float* __restrict__ bc,
    fp16* __restrict__ sph, fp16* __restrict__ spm, int sp_lda,
    fp16* __restrict__ hih, int t)
{
    const int b = blockIdx.x;
    if (b >= B_) return;
    float* zs  = (float*)smraw;          // 4*H floats
    float* red = zs + 4 * F_;            // 32 floats
    const float invH = 1.0f / (float)H;
    const size_t rowoff = (size_t)b * 4 * H;

    float s[4] = {0, 0, 0, 0}, q[4] = {0, 0, 0, 0};
    for (int u = threadIdx.x; u < H; u += blockDim.x) {
        #pragma unroll
        for (int ch = 0; ch < 4; ch++) {
            const int off = ch * H + u;
            float v = bias[off];
            for (int p = 0; p < nparts; p++)
                v += __ldcg(zp + (size_t)p * pstride + rowoff + off);
            zs[off] = v;
            s[ch] += v;
            q[ch] += v * v;
        }
    }
    __syncthreads();

    float mu[4], rs[4];
    #pragma unroll
    for (int ch = 0; ch < 4; ch++) {
        float smv = blockReduceSum(s[ch], red);
        float sq  = blockReduceSum(q[ch], red);
        mu[ch] = smv * invH;
        float var = sq * invH - mu[ch] * mu[ch];
        rs[ch] = rsqrtf(var + 1e-5f);
    }

    float nc_r[3], so_r[3];
    float sc_acc = 0.0f, qc_acc = 0.0f;
    #pragma unroll
    for (int it = 0; it < 3; it++) {
        int u = threadIdx.x + it * 256;
        if (u < H) {
            float iv = (zs[0 * H + u] - mu[0]) * rs[0] * gg[0 * H + u] + bg[0 * H + u];
            float jv = (zs[1 * H + u] - mu[1]) * rs[1] * gg[1 * H + u] + bg[1 * H + u];
            float fv = (zs[2 * H + u] - mu[2]) * rs[2] * gg[2 * H + u] + bg[2 * H + u];
            float ov = (zs[3 * H + u] - mu[3]) * rs[3] * gg[3 * H + u] + bg[3 * H + u];
            float cold = c[(size_t)b * H + u];
            float nc = cold * sigm(fv + 1.0f) + sigm(iv) * tanhf(jv);
            nc_r[it] = nc;
            so_r[it] = sigm(ov);
            sc_acc += nc;
            qc_acc += nc * nc;
        }
    }
    float smc = blockReduceSum(sc_acc, red);
    float sqc = blockReduceSum(qc_acc, red);
    float muc = smc * invH;
    float rsc = rsqrtf(sqc * invH - muc * muc + 1e-5f);

    #pragma unroll
    for (int it = 0; it < 3; it++) {
        int u = threadIdx.x + it * 256;
        if (u < H) {
            float nc = nc_r[it];
            float nh = tanhf((nc - muc) * rsc * gc[u] + bc[u]) * so_r[it];
            float hold = h[(size_t)b * H + u];
            float cold = c[(size_t)b * H + u];
            float hn = 0.9f * nh + 0.1f * hold;
            float cn = 0.5f * nc + 0.5f * cold;
            h[(size_t)b * H + u] = hn;
            c[(size_t)b * H + u] = cn;
            fp16 sh_, sm_;
            split2(hn, sh_, sm_);
            size_t so = (size_t)b * sp_lda + u;
            sph[so] = sh_; spm[so] = sm_;
            if (hih) hih[((size_t)b * T_ + t) * HI_LDA + u] = sh_;
        }
    }
}

// ---------------------------------------------------------------------------
// Persistent recurrence kernel: 100 steps x 6 phases, software grid barriers.
// ---------------------------------------------------------------------------
struct RecParams {
    const fp16 *xh, *xm;
    const float *b0, *g0, *bg0, *gc0, *bc0;
    const float *bS, *gS, *bgS, *gcS, *bcS;
    const float *b1, *g1, *bg1, *gc1, *bc1;
    const fp16 *W0h, *W0m, *WSh, *WSm, *W1h, *W1m;
    float *fh, *fc, *sh, *sc, *z, *zS;
    fp16 *fhh, *fhm, *shh, *shm, *hih;
};

__global__ void __launch_bounds__(256)
rec_persist(RecParams P)
{
    extern __shared__ char sm[];
    unsigned mygen = 0;
    const int psC = B_ * 4 * F_;
    const int psS = B_ * 4 * S_;

    for (int t = 0; t < T_; t++) {
        // Fast cell 0: A = [x_t | fh], Kpad=832, K1p=128
        gemm_phase(sm, P.xh + t * E_, P.xm + t * E_, T_ * E_, 128,
                   P.fhh, P.fhm, FH_LDA,
                   P.W0h, P.W0m, 832,
                   P.z, 4 * F_, psC, 832, 4 * F_, 44, KS_CELL);
        gbar(mygen);
        pw_phase(sm, P.z, psC, KS_CELL, P.b0, P.fh, P.fc, F_,
                 P.g0, P.bg0, P.gc0, P.bc0,
                 P.fhh, P.fhm, FH_LDA, nullptr, 0);
        gbar(mygen);

        // Slow cell: A = [fh | gap4 | sh], Kpad=1120, K1p=704
        gemm_phase(sm, P.fhh, P.fhm, FH_LDA, 704,
                   P.shh, P.shm, SH_LDA,
                   P.WSh, P.WSm, 1120,
                   P.zS, 4 * S_, psS, 1120, 4 * S_, 25, KS_SLOW);
        gbar(mygen);
        pw_phase(sm, P.zS, psS, KS_SLOW, P.bS, P.sh, P.sc, S_,
                 P.gS, P.bgS, P.gcS, P.bcS,
                 P.shh, P.shm, SH_LDA, nullptr, 0);
        gbar(mygen);

        // Fast cell 1: A = [sh | fh], Kpad=1120, K1p=400
        gemm_phase(sm, P.shh, P.shm, SH_LDA, 400,
                   P.fhh, P.fhm, FH_LDA,
                   P.W1h, P.W1m, 1120,
                   P.z, 4 * F_, psC, 1120, 4 * F_, 44, KS_CELL);
        gbar(mygen);
        pw_phase(sm, P.z, psC, KS_CELL, P.b1, P.fh, P.fc, F_,
                 P.g1, P.bg1, P.gc1, P.bc1,
                 P.fhh, P.fhm, FH_LDA, P.hih, t);
        gbar(mygen);
    }
}

// ---------------------------------------------------------------------------
// Projection GEMM (fp16 x2: Ah*Wh + Ah*Wm = round16(hist) @ W) — BN=128.
// ---------------------------------------------------------------------------
__global__ void __launch_bounds__(256)
gemm_proj(const fp16* __restrict__ Ah, long lda,
          const fp16* __restrict__ Wh, const fp16* __restrict__ Wm, int ldw,
          const float* __restrict__ bias,
          float* __restrict__ C, long ldc, int N, int Kpad)
{
    constexpr int NT  = 8;
    constexpr int BSZ = 128 * ARP;            // 10240
    constexpr uint32_t BBASE = 2 * ASZ;       // 20480

    extern __shared__ char sm[];
    const uint32_t sbase = smem_u32(sm);
    const int tid  = threadIdx.x;
    const int wid  = tid >> 5;
    const int lane = tid & 31;
    const int wm   = wid & 3;
    const int wn   = wid >> 2;
    const int n0   = blockIdx.x * 128;
    const long m0  = (long)blockIdx.y * 128;
    const int nk   = Kpad >> 5;

    const fp16* Ws[2] = {Wh, Wm};

    float acc[2][NT][4];
    #pragma unroll
    for (int mt = 0; mt < 2; mt++)
        #pragma unroll
        for (int nt = 0; nt < NT; nt++)
            #pragma unroll
            for (int r = 0; r < 4; r++) acc[mt][nt][r] = 0.0f;

    auto load_chunk = [&](int i) {
        const int k0 = i << 5;
        const int buf = i & 1;
        #pragma unroll
        for (int it = 0; it < 2; it++) {
            const int idx = (it << 8) + tid;
            const int r   = idx >> 2;
            const int c4  = idx & 3;
            CP16(sbase + buf * ASZ + r * ARP + c4 * 16,
                 Ah + (m0 + r) * lda + k0 + (c4 << 3), 16);
        }
        #pragma unroll
        for (int it = 0; it < 4; it++) {
            const int sp  = it >> 1;
            const int idx = ((it & 1) << 8) + tid;
            const int r   = idx >> 2;
            const int c4  = idx & 3;
            const int n   = n0 + r;
            const int nc  = (n < N) ? n : (N - 1);
            CP16(sbase + BBASE + sp * (2 * BSZ) + buf * BSZ + r * ARP + c4 * 16,
                 Ws[sp] + (long)nc * ldw + k0 + (c4 << 3), (n < N) ? 16 : 0);
        }
        CP_COMMIT();
    };

    load_chunk(0);
    for (int i = 0; i < nk; i++) {
        if (i + 1 < nk) { load_chunk(i + 1); CP_WAIT1(); }
        else            { CP_WAIT0(); }
        __syncthreads();
        const int buf = i & 1;

        #pragma unroll
        for (int ks = 0; ks < 2; ks++) {
            const uint32_t kb = (ks << 5) + ((lane & 3) << 2);
            uint32_t a[2][4];
            #pragma unroll
            for (int mt = 0; mt < 2; mt++) {
                const char* base = sm + buf * ASZ
                                 + (wm * 32 + mt * 16 + (lane >> 2)) * ARP + kb;
                a[mt][0] = *(const uint32_t*)(base);
                a[mt][1] = *(const uint32_t*)(base + 8 * ARP);
                a[mt][2] = *(const uint32_t*)(base + 16);
                a[mt][3] = *(const uint32_t*)(base + 8 * ARP + 16);
            }
            uint32_t b[2][NT][2];
            #pragma unroll
            for (int sp = 0; sp < 2; sp++)
                #pragma unroll
                for (int nt = 0; nt < NT; nt++) {
                    const char* base = sm + BBASE + sp * (2 * BSZ) + buf * BSZ
                                     + (wn * 64 + nt * 8 + (lane >> 2)) * ARP + kb;
                    b[sp][nt][0] = *(const uint32_t*)(base);
                    b[sp][nt][1] = *(const uint32_t*)(base + 16);
                }
            #pragma unroll
            for (int mt = 0; mt < 2; mt++)
                #pragma unroll
                for (int nt = 0; nt < NT; nt++) {
                    mma_fp16(acc[mt][nt], a[mt], b[1][nt]);  // H*Wm
                    mma_fp16(acc[mt][nt], a[mt], b[0][nt]);  // H*Wh
                }
        }
        __syncthreads();
    }

    #pragma unroll
    for (int mt = 0; mt < 2; mt++) {
        long gm = m0 + wm * 32 + mt * 16 + (lane >> 2);
        #pragma unroll
        for (int nt = 0; nt < NT; nt++) {
            int gn = n0 + wn * 64 + nt * 8 + ((lane & 3) << 1);
            if (gn < N) {
                float2 bv = *(const float2*)(bias + gn);
                *(float2*)(C + gm * ldc + gn) =
                    make_float2(acc[mt][nt][0] + bv.x, acc[mt][nt][1] + bv.y);
                *(float2*)(C + (gm + 8) * ldc + gn) =
                    make_float2(acc[mt][nt][2] + bv.x, acc[mt][nt][3] + bv.y);
            }
        }
    }
}

// ---------------------------------------------------------------------------
// Setup kernels
// ---------------------------------------------------------------------------
__global__ void transpose_split(const float* __restrict__ in,
                                fp16* __restrict__ oh, fp16* __restrict__ om,
                                int N, int ldw, int K1, int gap, int Ktot)
{
    long idx = (long)blockIdx.x * blockDim.x + threadIdx.x;
    long total = (long)N * ldw;
    if (idx >= total) return;
    int n = (int)(idx / ldw);
    int k = (int)(idx % ldw);
    float v = 0.0f;
    if (k < K1)                               v = in[(long)k * N + n];
    else if (k >= K1 + gap && k < Ktot + gap) v = in[(long)(k - gap) * N + n];
    fp16 h, m;
    split2(v, h, m);
    oh[idx] = h; om[idx] = m;
}

__global__ void split_inputs(const float* __restrict__ in)
{
    long idx = (long)blockIdx.x * blockDim.x + threadIdx.x;
    if (idx >= (long)B_ * T_ * E_) return;
    fp16 h, m;
    split2(in[idx], h, m);
    g_xh[idx] = h; g_xm[idx] = m;
}

__global__ void init_states()
{
    int i = blockIdx.x * blockDim.x + threadIdx.x;
    int stride = gridDim.x * blockDim.x;
    const fp16 hz = __float2half(0.0f);
    if (i == 0) { g_bargen = 0u; }
    for (int j = i; j < GRID_P * 8; j += stride) g_flags[j] = 0u;
    for (int j = i; j < B_ * F_; j += stride) { g_fh[j] = 0.0f; g_fc[j] = 0.0f; }
    for (int j = i; j < B_ * S_; j += stride) { g_sh[j] = 0.0f; g_sc[j] = 0.0f; }
    for (int j = i; j < B_ * FH_LDA; j += stride) { g_fhh[j] = hz; g_fhm[j] = hz; }
    for (int j = i; j < B_ * SH_LDA; j += stride) { g_shh[j] = hz; g_shm[j] = hz; }
    for (int j = i; j < B_ * T_ * 4; j += stride) {
        size_t off = (size_t)(j >> 2) * HI_LDA + F_ + (j & 3);
        g_hih[off] = hz;
    }
}

__global__ void tail_copy(float* __restrict__ out, size_t out_total)
{
    int i = blockIdx.x * blockDim.x + threadIdx.x;
    const size_t base = (size_t)B_ * T_ * V_;
    const int nF = B_ * F_, nS = B_ * S_;
    const int total = 2 * nF + 2 * nS;
    if (i >= total) return;
    float v;
    size_t off = base + i;
    if (i < nF)               v = g_fh[i];
    else if (i < 2 * nF)      v = g_fc[i - nF];
    else if (i < 2 * nF + nS) v = g_sh[i - 2 * nF];
    else                      v = g_sc[i - 2 * nF - nS];
    if (off < out_total) out[off] = v;
}

// ---------------------------------------------------------------------------
// Launch
// ---------------------------------------------------------------------------
extern "C" void kernel_launch(void* const* d_in, const int* in_sizes, int n_in,
                              void* d_out, int out_size)
{
    const float* inputs = (const float*)d_in[0];
    const float* W0  = (const float*)d_in[1];
    const float* b0  = (const float*)d_in[2];
    const float* g0  = (const float*)d_in[3];
    const float* bg0 = (const float*)d_in[4];
    const float* gc0 = (const float*)d_in[5];
    const float* bc0 = (const float*)d_in[6];
    const float* W1  = (const float*)d_in[7];
    const float* b1  = (const float*)d_in[8];
    const float* g1  = (const float*)d_in[9];
    const float* bg1 = (const float*)d_in[10];
    const float* gc1 = (const float*)d_in[11];
    const float* bc1 = (const float*)d_in[12];
    const float* WS  = (const float*)d_in[13];
    const float* bS  = (const float*)d_in[14];
    const float* gS  = (const float*)d_in[15];
    const float* bgS = (const float*)d_in[16];
    const float* gcS = (const float*)d_in[17];
    const float* bcS = (const float*)d_in[18];
    const float* Wout = (const float*)d_in[19];
    const float* bout = (const float*)d_in[20];
    float* out = (float*)d_out;

    RecParams P;
    float *z, *zS;
    fp16 *Woh, *Wom, *hih;
    cudaGetSymbolAddress((void**)&P.fh,  g_fh);  cudaGetSymbolAddress((void**)&P.fc,  g_fc);
    cudaGetSymbolAddress((void**)&P.sh,  g_sh);  cudaGetSymbolAddress((void**)&P.sc,  g_sc);
    cudaGetSymbolAddress((void**)&z,     g_z);   cudaGetSymbolAddress((void**)&zS,    g_zS);
    cudaGetSymbolAddress((void**)&P.xh,  g_xh);  cudaGetSymbolAddress((void**)&P.xm,  g_xm);
    cudaGetSymbolAddress((void**)&P.fhh, g_fhh); cudaGetSymbolAddress((void**)&P.fhm, g_fhm);
    cudaGetSymbolAddress((void**)&P.shh, g_shh); cudaGetSymbolAddress((void**)&P.shm, g_shm);
    cudaGetSymbolAddress((void**)&hih,   g_hih);
    cudaGetSymbolAddress((void**)&P.W0h, g_W0h); cudaGetSymbolAddress((void**)&P.W0m, g_W0m);
    cudaGetSymbolAddress((void**)&P.WSh, g_WSh); cudaGetSymbolAddress((void**)&P.WSm, g_WSm);
    cudaGetSymbolAddress((void**)&P.W1h, g_W1h); cudaGetSymbolAddress((void**)&P.W1m, g_W1m);
    cudaGetSymbolAddress((void**)&Woh,   g_Woh); cudaGetSymbolAddress((void**)&Wom,   g_Wom);
    P.z = z; P.zS = zS;
    P.hih = hih;
    P.b0 = b0; P.g0 = g0; P.bg0 = bg0; P.gc0 = gc0; P.bc0 = bc0;
    P.b1 = b1; P.g1 = g1; P.bg1 = bg1; P.gc1 = gc1; P.bc1 = bc1;
    P.bS = bS; P.gS = gS; P.bgS = bgS; P.gcS = gcS; P.bcS = bcS;

    const int SMP  = 4 * ASZ + 4 * (64 * ARP);    // 61440 (persistent)
    const int SMPR = 2 * ASZ + 4 * (128 * ARP);   // 61440 (projection)
    cudaFuncSetAttribute(rec_persist, cudaFuncAttributeMaxDynamicSharedMemorySize, SMP);
    cudaFuncSetAttribute(gemm_proj,   cudaFuncAttributeMaxDynamicSharedMemorySize, SMPR);

    // Weight transpose + split
    {
        long n;
        n = (long)4 * F_ * 832;
        transpose_split<<<(unsigned)((n + 255) / 256), 256>>>(W0, (fp16*)P.W0h, (fp16*)P.W0m, 4 * F_, 832, 828, 0, 828);
        n = (long)4 * S_ * 1120;
        transpose_split<<<(unsigned)((n + 255) / 256), 256>>>(WS, (fp16*)P.WSh, (fp16*)P.WSm, 4 * S_, 1120, 700, 4, 1100);
        n = (long)4 * F_ * 1120;
        transpose_split<<<(unsigned)((n + 255) / 256), 256>>>(W1, (fp16*)P.W1h, (fp16*)P.W1m, 4 * F_, 1120, 1100, 0, 1100);
        n = (long)V_ * 704;
        transpose_split<<<(unsigned)((n + 255) / 256), 256>>>(Wout, Woh, Wom, V_, 704, 700, 0, 700);
    }
    {
        long n = (long)B_ * T_ * E_;
        split_inputs<<<(unsigned)((n + 255) / 256), 256>>>(inputs);
    }
    init_states<<<148, 256>>>();

    // Entire recurrence: ONE persistent kernel
    rec_persist<<<GRID_P, 256, SMP>>>(P);

    // Output projection: round16(hist)[12800,704] @ Wout^T + bias
    {
        const dim3 grid((V_ + 127) / 128, (B_ * T_) / 128, 1);   // 79 x 100
        gemm_proj<<<grid, 256, SMPR>>>(
            hih, HI_LDA, Woh, Wom, 704, bout, out, V_, V_, 704);
    }

    {
        int total = 2 * B_ * F_ + 2 * B_ * S_;
        tail_copy<<<(total + 255) / 256, 256>>>(out, (size_t)out_size);
    }
}

// round 13
// speedup vs baseline: 7.6991x; 1.1918x over previous
#include <cuda_runtime.h>
#include <cuda_fp16.h>
#include <cstdint>

// Problem constants
#define B_  128
#define T_  100
#define E_  128
#define F_  700
#define S_  400
#define V_  10000

#define FH_LDA 720
#define SH_LDA 424
#define HI_LDA 704

#define KS_CELL 3
#define KS_SLOW 5
#define GRID_P  132          // persistent grid (44*3)

typedef __half fp16;

// ---------------------------------------------------------------------------
// Static device scratch
// ---------------------------------------------------------------------------
__device__ float g_fh[B_ * F_];
__device__ float g_fc[B_ * F_];
__device__ float g_sh[B_ * S_];
__device__ float g_sc[B_ * S_];
__device__ float g_z [KS_CELL * B_ * 4 * F_];
__device__ float g_zS[KS_SLOW * B_ * 4 * S_];

__device__ fp16 g_xh[B_ * T_ * E_], g_xm[B_ * T_ * E_];
__device__ fp16 g_fhh[B_ * FH_LDA], g_fhm[B_ * FH_LDA];
__device__ fp16 g_shh[B_ * SH_LDA], g_shm[B_ * SH_LDA];
__device__ fp16 g_hih[(size_t)B_ * T_ * HI_LDA];          // hist high split only

__device__ fp16 g_W0h[(size_t)4 * F_ * 832],  g_W0m[(size_t)4 * F_ * 832];
__device__ fp16 g_WSh[(size_t)4 * S_ * 1120], g_WSm[(size_t)4 * S_ * 1120];
__device__ fp16 g_W1h[(size_t)4 * F_ * 1120], g_W1m[(size_t)4 * F_ * 1120];
__device__ fp16 g_Woh[(size_t)V_ * 704];

// Grid barrier state: per-CTA arrival flags (32B stride) + release word
__device__ unsigned g_flags[GRID_P * 8];
__device__ unsigned g_bargen;

// ---------------------------------------------------------------------------
// Helpers
// ---------------------------------------------------------------------------
__device__ __forceinline__ uint32_t smem_u32(const void* p) {
    uint32_t a;
    asm("{ .reg .u64 t; cvta.to.shared.u64 t, %1; cvt.u32.u64 %0, t; }" : "=r"(a) : "l"(p));
    return a;
}
__device__ __forceinline__ void split2(float x, fp16& h, fp16& m) {
    h = __float2half_rn(x);
    m = __float2half_rn(x - __half2float(h));
}
__device__ __forceinline__ void mma_fp16(float c[4], const uint32_t a[4], const uint32_t b[2]) {
    asm volatile("mma.sync.aligned.m16n8k16.row.col.f32.f16.f16.f32 "
                 "{%0,%1,%2,%3}, {%4,%5,%6,%7}, {%8,%9}, {%0,%1,%2,%3};"
                 : "+f"(c[0]), "+f"(c[1]), "+f"(c[2]), "+f"(c[3])
                 : "r"(a[0]), "r"(a[1]), "r"(a[2]), "r"(a[3]), "r"(b[0]), "r"(b[1]));
}
#define CP16(dst, src, sz) \
    asm volatile("cp.async.cg.shared.global [%0], [%1], 16, %2;" \
                 :: "r"(dst), "l"(src), "r"(sz))
#define CP_COMMIT() asm volatile("cp.async.commit_group;" ::: "memory")
#define CP_WAIT1()  asm volatile("cp.async.wait_group 1;" ::: "memory")
#define CP_WAIT0()  asm volatile("cp.async.wait_group 0;" ::: "memory")

#define ARP   80
#define ASZ   (128 * ARP)            // 10240 bytes per A split-buffer

// ---------------------------------------------------------------------------
// Fast grid barrier: parallel flag stores + CTA0 gather + single release word.
// ---------------------------------------------------------------------------
__device__ __forceinline__ void gbar(unsigned& mygen) {
    mygen++;
    __syncthreads();
    __threadfence();
    if (threadIdx.x == 0)
        *((volatile unsigned*)&g_flags[blockIdx.x * 8]) = mygen;
    if (blockIdx.x == 0) {
        if (threadIdx.x < GRID_P) {
            volatile unsigned* f = &g_flags[threadIdx.x * 8];
            while (*f < mygen) {}
        }
        __syncthreads();
        if (threadIdx.x == 0) {
            __threadfence();
            *((volatile unsigned*)&g_bargen) = mygen;
        }
    } else {
        if (threadIdx.x == 0) {
            volatile unsigned* g = &g_bargen;
            while (*g < mygen) {}
        }
    }
    __syncthreads();
    __threadfence();
}

// ---------------------------------------------------------------------------
// GEMM phase (device fn), BN=64, fp16 2-way split, 3 products:
//   HM + MH chained in-MMA (|.| ~ 2^-11), H*H via zero-C MMA + IEEE FADD.
// Writes split-K partials (no bias). M = 128 fixed.
// ---------------------------------------------------------------------------
__device__ void gemm_phase(char* sm,
    const fp16* __restrict__ A1h, const fp16* __restrict__ A1m,
    int lda1, int K1p,
    const fp16* __restrict__ A2h, const fp16* __restrict__ A2m,
    int lda2,
    const fp16* __restrict__ Wh, const fp16* __restrict__ Wm,
    int ldw,
    float* __restrict__ C, int ldc, int pstride,
    int Kpad, int N, int tnc, int KS)
{
    constexpr int NT  = 4;
    constexpr int BSZ = 64 * ARP;             // 5120
    constexpr uint32_t BBASE = 4 * ASZ;       // 40960

    const int cta = blockIdx.x;
    if (cta >= tnc * KS) return;

    const uint32_t sbase = smem_u32(sm);
    const int tid  = threadIdx.x;
    const int wid  = tid >> 5;
    const int lane = tid & 31;
    const int wm   = wid & 3;
    const int wn   = wid >> 2;
    const int n0   = (cta % tnc) * 64;
    const int kz   = cta / tnc;
    const int nk   = Kpad >> 5;
    const int nkq  = (nk + KS - 1) / KS;
    const int i0   = kz * nkq;
    const int i1   = (i0 + nkq < nk) ? (i0 + nkq) : nk;

    const fp16* A1s[2] = {A1h, A1m};
    const fp16* A2s[2] = {A2h, A2m};
    const fp16* Ws [2] = {Wh,  Wm};

    float acc[2][NT][4], accs[2][NT][4];
    #pragma unroll
    for (int mt = 0; mt < 2; mt++)
        #pragma unroll
        for (int nt = 0; nt < NT; nt++)
            #pragma unroll
            for (int r = 0; r < 4; r++) { acc[mt][nt][r] = 0.0f; accs[mt][nt][r] = 0.0f; }

    auto load_chunk = [&](int i) {
        const int k0 = i << 5;
        const int buf = i & 1;
        #pragma unroll
        for (int it = 0; it < 4; it++) {
            const int sp  = it >> 1;
            const int idx = ((it & 1) << 8) + tid;
            const int r   = idx >> 2;
            const int c4  = idx & 3;
            const int gk  = k0 + (c4 << 3);
            const fp16* src = (gk < K1p) ? A1s[sp] + r * lda1 + gk
                                         : A2s[sp] + r * lda2 + (gk - K1p);
            CP16(sbase + sp * (2 * ASZ) + buf * ASZ + r * ARP + c4 * 16, src, 16);
        }
        #pragma unroll
        for (int it = 0; it < 2; it++) {
            const int sp  = it;
            const int r   = tid >> 2;
            const int c4  = tid & 3;
            const int n   = n0 + r;
            const int nc  = (n < N) ? n : (N - 1);
            const fp16* src = Ws[sp] + (long)nc * ldw + k0 + (c4 << 3);
            CP16(sbase + BBASE + sp * (2 * BSZ) + buf * BSZ + r * ARP + c4 * 16,
                 src, (n < N) ? 16 : 0);
        }
        CP_COMMIT();
    };

    if (i0 < i1) load_chunk(i0);
    for (int i = i0; i < i1; i++) {
        if (i + 1 < i1) { load_chunk(i + 1); CP_WAIT1(); }
        else            { CP_WAIT0(); }
        __syncthreads();
        const int buf = i & 1;

        #pragma unroll
        for (int ks = 0; ks < 2; ks++) {
            const uint32_t kb = (ks << 5) + ((lane & 3) << 2);
            uint32_t a[2][2][4];
            #pragma unroll
            for (int sp = 0; sp < 2; sp++)
                #pragma unroll
                for (int mt = 0; mt < 2; mt++) {
                    const char* base = sm + sp * (2 * ASZ) + buf * ASZ
                                     + (wm * 32 + mt * 16 + (lane >> 2)) * ARP + kb;
                    a[sp][mt][0] = *(const uint32_t*)(base);
                    a[sp][mt][1] = *(const uint32_t*)(base + 8 * ARP);
                    a[sp][mt][2] = *(const uint32_t*)(base + 16);
                    a[sp][mt][3] = *(const uint32_t*)(base + 8 * ARP + 16);
                }
            uint32_t b[2][NT][2];
            #pragma unroll
            for (int sp = 0; sp < 2; sp++)
                #pragma unroll
                for (int nt = 0; nt < NT; nt++) {
                    const char* base = sm + BBASE + sp * (2 * BSZ) + buf * BSZ
                                     + (wn * 32 + nt * 8 + (lane >> 2)) * ARP + kb;
                    b[sp][nt][0] = *(const uint32_t*)(base);
                    b[sp][nt][1] = *(const uint32_t*)(base + 16);
                }
            #pragma unroll
            for (int mt = 0; mt < 2; mt++)
                #pragma unroll
                for (int nt = 0; nt < NT; nt++) {
                    mma_fp16(accs[mt][nt], a[0][mt], b[1][nt]);  // H*M (~2^-11)
                    mma_fp16(accs[mt][nt], a[1][mt], b[0][nt]);  // M*H (~2^-11)
                    float d[4] = {0.f, 0.f, 0.f, 0.f};           // H*H unchained
                    mma_fp16(d, a[0][mt], b[0][nt]);
                    acc[mt][nt][0] += d[0];
                    acc[mt][nt][1] += d[1];
                    acc[mt][nt][2] += d[2];
                    acc[mt][nt][3] += d[3];
                }
        }
        __syncthreads();
    }

    float* Cp = C + (size_t)kz * pstride;
    #pragma unroll
    for (int mt = 0; mt < 2; mt++) {
        int gm = wm * 32 + mt * 16 + (lane >> 2);
        #pragma unroll
        for (int nt = 0; nt < NT; nt++) {
            int gn = n0 + wn * 32 + nt * 8 + ((lane & 3) << 1);
            if (gn < N) {
                float r0 = acc[mt][nt][0] + accs[mt][nt][0];
                float r1 = acc[mt][nt][1] + accs[mt][nt][1];
                float r2 = acc[mt][nt][2] + accs[mt][nt][2];
                float r3 = acc[mt][nt][3] + accs[mt][nt][3];
                *(float2*)(Cp + (size_t)gm * ldc + gn)       = make_float2(r0, r1);
                *(float2*)(Cp + (size_t)(gm + 8) * ldc + gn) = make_float2(r2, r3);
            }
        }
    }
}

// ---------------------------------------------------------------------------
// Pointwise phase. Batched block reductions (one smem pass for NV stats).
// ---------------------------------------------------------------------------
__device__ __forceinline__ float sigm(float x) { return 1.0f / (1.0f + __expf(-x)); }

template <int NV>
__device__ __forceinline__ void blockReduceN(float* v, float* red) {
    const int lane = threadIdx.x & 31;
    const int w    = threadIdx.x >> 5;
    #pragma unroll
    for (int i = 0; i < NV; i++)
        #pragma unroll
        for (int o = 16; o > 0; o >>= 1) v[i] += __shfl_down_sync(0xffffffffu, v[i], o);
    if (lane == 0)
        #pragma unroll
        for (int i = 0; i < NV; i++) red[w * NV + i] = v[i];
    __syncthreads();
    if (threadIdx.x < NV) {
        float s = 0.0f;
        #pragma unroll
        for (int j = 0; j < 8; j++) s += red[j * NV + threadIdx.x];
        red[8 * NV + threadIdx.x] = s;
    }
    __syncthreads();
    #pragma unroll
    for (int i = 0; i < NV; i++) v[i] = red[8 * NV + i];
    __syncthreads();
}

__device__ void pw_phase(char* smraw,
    const float* __restrict__ zp, int pstride, int nparts,
    const float* __restrict__ bias,
    float* __restrict__ h, float* __restrict__ c, int H,
    const float* __restrict__ gg, const float* __restrict__ bg,
    const float* __restrict__ gc, const float* __restrict__ bc,
    fp16* __restrict__ sph, fp16* __restrict__ spm, int sp_lda,
    fp16* __restrict__ hih, int t)
{
    const int b = blockIdx.x;
    if (b >= B_) return;
    float* zs  = (float*)smraw;          // 4*H floats
    float* red = zs + 4 * F_;            // 72 floats
    const float invH = 1.0f / (float)H;
    const size_t rowoff = (size_t)b * 4 * H;

    float st[8] = {0, 0, 0, 0, 0, 0, 0, 0};   // [0:4) sums, [4:8) sumsq
    for (int u = threadIdx.x; u < H; u += blockDim.x) {
        #pragma unroll
        for (int ch = 0; ch < 4; ch++) {
            const int off = ch * H + u;
            float v = bias[off];
            for (int p = 0; p < nparts; p++)
                v += __ldcg(zp + (size_t)p * pstride + rowoff + off);
            zs[off] = v;
            st[ch]     += v;
            st[4 + ch] += v * v;
        }
    }
    __syncthreads();
    blockReduceN<8>(st, red);

    float mu[4], rs[4];
    #pragma unroll
    for (int ch = 0; ch < 4; ch++) {
        mu[ch] = st[ch] * invH;
        float var = st[4 + ch] * invH - mu[ch] * mu[ch];
        rs[ch] = rsqrtf(var + 1e-5f);
    }

    float nc_r[3], so_r[3];
    float cst[2] = {0.0f, 0.0f};
    #pragma unroll
    for (int it = 0; it < 3; it++) {
        int u = threadIdx.x + it * 256;
        if (u < H) {
            float iv = (zs[0 * H + u] - mu[0]) * rs[0] * gg[0 * H + u] + bg[0 * H + u];
            float jv = (zs[1 * H + u] - mu[1]) * rs[1] * gg[1 * H + u] + bg[1 * H + u];
            float fv = (zs[2 * H + u] - mu[2]) * rs[2] * gg[2 * H + u] + bg[2 * H + u];
            float ov = (zs[3 * H + u] - mu[3]) * rs[3] * gg[3 * H + u] + bg[3 * H + u];
            float cold = c[(size_t)b * H + u];
            float nc = cold * sigm(fv + 1.0f) + sigm(iv) * tanhf(jv);
            nc_r[it] = nc;
            so_r[it] = sigm(ov);
            cst[0] += nc;
            cst[1] += nc * nc;
        }
    }
    blockReduceN<2>(cst, red);
    float muc = cst[0] * invH;
    float rsc = rsqrtf(cst[1] * invH - muc * muc + 1e-5f);

    #pragma unroll
    for (int it = 0; it < 3; it++) {
        int u = threadIdx.x + it * 256;
        if (u < H) {
            float nc = nc_r[it];
            float nh = tanhf((nc - muc) * rsc * gc[u] + bc[u]) * so_r[it];
            float hold = h[(size_t)b * H + u];
            float cold = c[(size_t)b * H + u];
            float hn = 0.9f * nh + 0.1f * hold;
            float cn = 0.5f * nc + 0.5f * cold;
            h[(size_t)b * H + u] = hn;
            c[(size_t)b * H + u] = cn;
            fp16 sh_, sm_;
            split2(hn, sh_, sm_);
            size_t so = (size_t)b * sp_lda + u;
            sph[so] = sh_; spm[so] = sm_;
            if (hih) hih[((size_t)b * T_ + t) * HI_LDA + u] = sh_;
        }
    }
}

// ---------------------------------------------------------------------------
// Persistent recurrence kernel: 100 steps x 6 phases, software grid barriers.
// ---------------------------------------------------------------------------
struct RecParams {
    const fp16 *xh, *xm;
    const float *b0, *g0, *bg0, *gc0, *bc0;
    const float *bS, *gS, *bgS, *gcS, *bcS;
    const float *b1, *g1, *bg1, *gc1, *bc1;
    const fp16 *W0h, *W0m, *WSh, *WSm, *W1h, *W1m;
    float *fh, *fc, *sh, *sc, *z, *zS;
    fp16 *fhh, *fhm, *shh, *shm, *hih;
};

__global__ void __launch_bounds__(256)
rec_persist(RecParams P)
{
    extern __shared__ char sm[];
    unsigned mygen = 0;
    const int psC = B_ * 4 * F_;
    const int psS = B_ * 4 * S_;

    for (int t = 0; t < T_; t++) {
        // Fast cell 0: A = [x_t | fh], Kpad=832, K1p=128
        gemm_phase(sm, P.xh + t * E_, P.xm + t * E_, T_ * E_, 128,
                   P.fhh, P.fhm, FH_LDA,
                   P.W0h, P.W0m, 832,
                   P.z, 4 * F_, psC, 832, 4 * F_, 44, KS_CELL);
        gbar(mygen);
        pw_phase(sm, P.z, psC, KS_CELL, P.b0, P.fh, P.fc, F_,
                 P.g0, P.bg0, P.gc0, P.bc0,
                 P.fhh, P.fhm, FH_LDA, nullptr, 0);
        gbar(mygen);

        // Slow cell: A = [fh | gap4 | sh], Kpad=1120, K1p=704
        gemm_phase(sm, P.fhh, P.fhm, FH_LDA, 704,
                   P.shh, P.shm, SH_LDA,
                   P.WSh, P.WSm, 1120,
                   P.zS, 4 * S_, psS, 1120, 4 * S_, 25, KS_SLOW);
        gbar(mygen);
        pw_phase(sm, P.zS, psS, KS_SLOW, P.bS, P.sh, P.sc, S_,
                 P.gS, P.bgS, P.gcS, P.bcS,
                 P.shh, P.shm, SH_LDA, nullptr, 0);
        gbar(mygen);

        // Fast cell 1: A = [sh | fh], Kpad=1120, K1p=400
        gemm_phase(sm, P.shh, P.shm, SH_LDA, 400,
                   P.fhh, P.fhm, FH_LDA,
                   P.W1h, P.W1m, 1120,
                   P.z, 4 * F_, psC, 1120, 4 * F_, 44, KS_CELL);
        gbar(mygen);
        pw_phase(sm, P.z, psC, KS_CELL, P.b1, P.fh, P.fc, F_,
                 P.g1, P.bg1, P.gc1, P.bc1,
                 P.fhh, P.fhm, FH_LDA, P.hih, t);
        gbar(mygen);
    }
}

// ---------------------------------------------------------------------------
// Projection GEMM (pure fp16 x1: round16(hist) @ round16(W)) — BN=128.
// ---------------------------------------------------------------------------
__global__ void __launch_bounds__(256)
gemm_proj(const fp16* __restrict__ Ah, long lda,
          const fp16* __restrict__ Wh, int ldw,
          const float* __restrict__ bias,
          float* __restrict__ C, long ldc, int N, int Kpad)
{
    constexpr int NT  = 8;
    constexpr int BSZ = 128 * ARP;            // 10240
    constexpr uint32_t BBASE = 2 * ASZ;       // 20480

    extern __shared__ char sm[];
    const uint32_t sbase = smem_u32(sm);
    const int tid  = threadIdx.x;
    const int wid  = tid >> 5;
    const int lane = tid & 31;
    const int wm   = wid & 3;
    const int wn   = wid >> 2;
    const int n0   = blockIdx.x * 128;
    const long m0  = (long)blockIdx.y * 128;
    const int nk   = Kpad >> 5;

    float acc[2][NT][4];
    #pragma unroll
    for (int mt = 0; mt < 2; mt++)
        #pragma unroll
        for (int nt = 0; nt < NT; nt++)
            #pragma unroll
            for (int r = 0; r < 4; r++) acc[mt][nt][r] = 0.0f;

    auto load_chunk = [&](int i) {
        const int k0 = i << 5;
        const int buf = i & 1;
        #pragma unroll
        for (int it = 0; it < 2; it++) {
            const int idx = (it << 8) + tid;
            const int r   = idx >> 2;
            const int c4  = idx & 3;
            CP16(sbase + buf * ASZ + r * ARP + c4 * 16,
                 Ah + (m0 + r) * lda + k0 + (c4 << 3), 16);
        }
        #pragma unroll
        for (int it = 0; it < 2; it++) {
            const int idx = (it << 8) + tid;
            const int r   = idx >> 2;
            const int c4  = idx & 3;
            const int n   = n0 + r;
            const int nc  = (n < N) ? n : (N - 1);
            CP16(sbase + BBASE + buf * BSZ + r * ARP + c4 * 16,
                 Wh + (long)nc * ldw + k0 + (c4 << 3), (n < N) ? 16 : 0);
        }
        CP_COMMIT();
    };

    load_chunk(0);
    for (int i = 0; i < nk; i++) {
        if (i + 1 < nk) { load_chunk(i + 1); CP_WAIT1(); }
        else            { CP_WAIT0(); }
        __syncthreads();
        const int buf = i & 1;

        #pragma unroll
        for (int ks = 0; ks < 2; ks++) {
            const uint32_t kb = (ks << 5) + ((lane & 3) << 2);
            uint32_t a[2][4];
            #pragma unroll
            for (int mt = 0; mt < 2; mt++) {
                const char* base = sm + buf * ASZ
                                 + (wm * 32 + mt * 16 + (lane >> 2)) * ARP + kb;
                a[mt][0] = *(const uint32_t*)(base);
                a[mt][1] = *(const uint32_t*)(base + 8 * ARP);
                a[mt][2] = *(const uint32_t*)(base + 16);
                a[mt][3] = *(const uint32_t*)(base + 8 * ARP + 16);
            }
            uint32_t b[NT][2];
            #pragma unroll
            for (int nt = 0; nt < NT; nt++) {
                const char* base = sm + BBASE + buf * BSZ
                                 + (wn * 64 + nt * 8 + (lane >> 2)) * ARP + kb;
                b[nt][0] = *(const uint32_t*)(base);
                b[nt][1] = *(const uint32_t*)(base + 16);
            }
            #pragma unroll
            for (int mt = 0; mt < 2; mt++)
                #pragma unroll
                for (int nt = 0; nt < NT; nt++)
                    mma_fp16(acc[mt][nt], a[mt], b[nt]);
        }
        __syncthreads();
    }

    #pragma unroll
    for (int mt = 0; mt < 2; mt++) {
        long gm = m0 + wm * 32 + mt * 16 + (lane >> 2);
        #pragma unroll
        for (int nt = 0; nt < NT; nt++) {
            int gn = n0 + wn * 64 + nt * 8 + ((lane & 3) << 1);
            if (gn < N) {
                float2 bv = *(const float2*)(bias + gn);
                *(float2*)(C + gm * ldc + gn) =
                    make_float2(acc[mt][nt][0] + bv.x, acc[mt][nt][1] + bv.y);
                *(float2*)(C + (gm + 8) * ldc + gn) =
                    make_float2(acc[mt][nt][2] + bv.x, acc[mt][nt][3] + bv.y);
            }
        }
    }
}

// ---------------------------------------------------------------------------
// Setup kernels
// ---------------------------------------------------------------------------
__global__ void transpose_split(const float* __restrict__ in,
                                fp16* __restrict__ oh, fp16* __restrict__ om,
                                int N, int ldw, int K1, int gap, int Ktot)
{
    long idx = (long)blockIdx.x * blockDim.x + threadIdx.x;
    long total = (long)N * ldw;
    if (idx >= total) return;
    int n = (int)(idx / ldw);
    int k = (int)(idx % ldw);
    float v = 0.0f;
    if (k < K1)                               v = in[(long)k * N + n];
    else if (k >= K1 + gap && k < Ktot + gap) v = in[(long)(k - gap) * N + n];
    fp16 h, m;
    split2(v, h, m);
    oh[idx] = h;
    if (om) om[idx] = m;
}

__global__ void split_inputs(const float* __restrict__ in)
{
    long idx = (long)blockIdx.x * blockDim.x + threadIdx.x;
    if (idx >= (long)B_ * T_ * E_) return;
    fp16 h, m;
    split2(in[idx], h, m);
    g_xh[idx] = h; g_xm[idx] = m;
}

__global__ void init_states()
{
    int i = blockIdx.x * blockDim.x + threadIdx.x;
    int stride = gridDim.x * blockDim.x;
    const fp16 hz = __float2half(0.0f);
    if (i == 0) { g_bargen = 0u; }
    for (int j = i; j < GRID_P * 8; j += stride) g_flags[j] = 0u;
    for (int j = i; j < B_ * F_; j += stride) { g_fh[j] = 0.0f; g_fc[j] = 0.0f; }
    for (int j = i; j < B_ * S_; j += stride) { g_sh[j] = 0.0f; g_sc[j] = 0.0f; }
    for (int j = i; j < B_ * FH_LDA; j += stride) { g_fhh[j] = hz; g_fhm[j] = hz; }
    for (int j = i; j < B_ * SH_LDA; j += stride) { g_shh[j] = hz; g_shm[j] = hz; }
    for (int j = i; j < B_ * T_ * 4; j += stride) {
        size_t off = (size_t)(j >> 2) * HI_LDA + F_ + (j & 3);
        g_hih[off] = hz;
    }
}

__global__ void tail_copy(float* __restrict__ out, size_t out_total)
{
    int i = blockIdx.x * blockDim.x + threadIdx.x;
    const size_t base = (size_t)B_ * T_ * V_;
    const int nF = B_ * F_, nS = B_ * S_;
    const int total = 2 * nF + 2 * nS;
    if (i >= total) return;
    float v;
    size_t off = base + i;
    if (i < nF)               v = g_fh[i];
    else if (i < 2 * nF)      v = g_fc[i - nF];
    else if (i < 2 * nF + nS) v = g_sh[i - 2 * nF];
    else                      v = g_sc[i - 2 * nF - nS];
    if (off < out_total) out[off] = v;
}

// ---------------------------------------------------------------------------
// Launch
// ---------------------------------------------------------------------------
extern "C" void kernel_launch(void* const* d_in, const int* in_sizes, int n_in,
                              void* d_out, int out_size)
{
    const float* inputs = (const float*)d_in[0];
    const float* W0  = (const float*)d_in[1];
    const float* b0  = (const float*)d_in[2];
    const float* g0  = (const float*)d_in[3];
    const float* bg0 = (const float*)d_in[4];
    const float* gc0 = (const float*)d_in[5];
    const float* bc0 = (const float*)d_in[6];
    const float* W1  = (const float*)d_in[7];
    const float* b1  = (const float*)d_in[8];
    const float* g1  = (const float*)d_in[9];
    const float* bg1 = (const float*)d_in[10];
    const float* gc1 = (const float*)d_in[11];
    const float* bc1 = (const float*)d_in[12];
    const float* WS  = (const float*)d_in[13];
    const float* bS  = (const float*)d_in[14];
    const float* gS  = (const float*)d_in[15];
    const float* bgS = (const float*)d_in[16];
    const float* gcS = (const float*)d_in[17];
    const float* bcS = (const float*)d_in[18];
    const float* Wout = (const float*)d_in[19];
    const float* bout = (const float*)d_in[20];
    float* out = (float*)d_out;

    RecParams P;
    float *z, *zS;
    fp16 *Woh, *hih;
    cudaGetSymbolAddress((void**)&P.fh,  g_fh);  cudaGetSymbolAddress((void**)&P.fc,  g_fc);
    cudaGetSymbolAddress((void**)&P.sh,  g_sh);  cudaGetSymbolAddress((void**)&P.sc,  g_sc);
    cudaGetSymbolAddress((void**)&z,     g_z);   cudaGetSymbolAddress((void**)&zS,    g_zS);
    cudaGetSymbolAddress((void**)&P.xh,  g_xh);  cudaGetSymbolAddress((void**)&P.xm,  g_xm);
    cudaGetSymbolAddress((void**)&P.fhh, g_fhh); cudaGetSymbolAddress((void**)&P.fhm, g_fhm);
    cudaGetSymbolAddress((void**)&P.shh, g_shh); cudaGetSymbolAddress((void**)&P.shm, g_shm);
    cudaGetSymbolAddress((void**)&hih,   g_hih);
    cudaGetSymbolAddress((void**)&P.W0h, g_W0h); cudaGetSymbolAddress((void**)&P.W0m, g_W0m);
    cudaGetSymbolAddress((void**)&P.WSh, g_WSh); cudaGetSymbolAddress((void**)&P.WSm, g_WSm);
    cudaGetSymbolAddress((void**)&P.W1h, g_W1h); cudaGetSymbolAddress((void**)&P.W1m, g_W1m);
    cudaGetSymbolAddress((void**)&Woh,   g_Woh);
    P.z = z; P.zS = zS;
    P.hih = hih;
    P.b0 = b0; P.g0 = g0; P.bg0 = bg0; P.gc0 = gc0; P.bc0 = bc0;
    P.b1 = b1; P.g1 = g1; P.bg1 = bg1; P.gc1 = gc1; P.bc1 = bc1;
    P.bS = bS; P.gS = gS; P.bgS = bgS; P.gcS = gcS; P.bcS = bcS;

    const int SMP  = 4 * ASZ + 4 * (64 * ARP);    // 61440 (persistent)
    const int SMPR = 2 * ASZ + 2 * (128 * ARP);   // 40960 (projection)
    cudaFuncSetAttribute(rec_persist, cudaFuncAttributeMaxDynamicSharedMemorySize, SMP);
    cudaFuncSetAttribute(gemm_proj,   cudaFuncAttributeMaxDynamicSharedMemorySize, SMPR);

    // Weight transpose + split
    {
        long n;
        n = (long)4 * F_ * 832;
        transpose_split<<<(unsigned)((n + 255) / 256), 256>>>(W0, (fp16*)P.W0h, (fp16*)P.W0m, 4 * F_, 832, 828, 0, 828);
        n = (long)4 * S_ * 1120;
        transpose_split<<<(unsigned)((n + 255) / 256), 256>>>(WS, (fp16*)P.WSh, (fp16*)P.WSm, 4 * S_, 1120, 700, 4, 1100);
        n = (long)4 * F_ * 1120;
        transpose_split<<<(unsigned)((n + 255) / 256), 256>>>(W1, (fp16*)P.W1h, (fp16*)P.W1m, 4 * F_, 1120, 1100, 0, 1100);
        n = (long)V_ * 704;
        transpose_split<<<(unsigned)((n + 255) / 256), 256>>>(Wout, Woh, (fp16*)nullptr, V_, 704, 700, 0, 700);
    }
    {
        long n = (long)B_ * T_ * E_;
        split_inputs<<<(unsigned)((n + 255) / 256), 256>>>(inputs);
    }
    init_states<<<148, 256>>>();

    // Entire recurrence: ONE persistent kernel
    rec_persist<<<GRID_P, 256, SMP>>>(P);

    // Output projection: round16(hist)[12800,704] @ round16(Wout) + bias
    {
        const dim3 grid((V_ + 127) / 128, (B_ * T_) / 128, 1);   // 79 x 100
        gemm_proj<<<grid, 256, SMPR>>>(
            hih, HI_LDA, Woh, 704, bout, out, V_, V_, 704);
    }

    {
        int total = 2 * B_ * F_ + 2 * B_ * S_;
        tail_copy<<<(total + 255) / 256, 256>>>(out, (size_t)out_size);
    }
}